// round 15
// baseline (speedup 1.0000x reference)
#include <cuda_runtime.h>
#include <cuda_bf16.h>
#include <math.h>
#include <stdint.h>

#define NP 325632   // 1272 * 256 : columns of the big GEMMs, p = t*256 + b

// ---------------- scratch (device globals; no allocation) ----------------
__device__ float g_r1[10485760];     // stream ping: bf16 planes XH/XL [q][32]
__device__ float g_r2[10485760];     // stream pong
__device__ float g_G[62521344];      // bf16 planes: GtH [NP][192], GtL [NP][192]
__device__ float g_skip[83361792];   // reused: wfc1H/L bf16 [1024][10144], we2H/L [32][128]
__device__ float g_y1[41680896];     // bf16 planes y1H/[NP][128], y1L
__device__ float g_y2[5201920];      // bf16 planes y2H/[162560][32], y2L
__device__ float g_p2[2596864];      // bf16 planes p2H/[81152][32], p2L
__device__ float g_f1p[2097152];     // split-K partials (fc1: 8x1024x256; fc2: 8x256x256)
__device__ float g_f1[262144];       // 1024 x 256
__device__ float g_f2[65536];        // 256 x 256
__device__ __nv_bfloat16 g_wtc[163840]; // wskH[49152] wskL[49152] we1H[32768] we1L[32768]
__device__ __nv_bfloat16 g_wlay[61440]; // per-layer: WfgH[4096] WfgL[4096] WrH[1024] WrL[1024]

// ================= mma.sync helpers (sm_80+ portable) =================
__device__ __forceinline__ uint32_t s2u(const void* p) {
    uint32_t a;
    asm("{ .reg .u64 t; cvta.to.shared.u64 t, %1; cvt.u32.u64 %0, t; }" : "=r"(a) : "l"(p));
    return a;
}
__device__ __forceinline__ void ldm_x4(uint32_t* r, uint32_t addr) {
    asm volatile("ldmatrix.sync.aligned.m8n8.x4.shared.b16 {%0,%1,%2,%3}, [%4];"
                 : "=r"(r[0]), "=r"(r[1]), "=r"(r[2]), "=r"(r[3]) : "r"(addr));
}
__device__ __forceinline__ void ldm_x2(uint32_t* r, uint32_t addr) {
    asm volatile("ldmatrix.sync.aligned.m8n8.x2.shared.b16 {%0,%1}, [%2];"
                 : "=r"(r[0]), "=r"(r[1]) : "r"(addr));
}
__device__ __forceinline__ void mma16816(float* c, const uint32_t* a, const uint32_t* b) {
    asm volatile(
        "mma.sync.aligned.m16n8k16.row.col.f32.bf16.bf16.f32 "
        "{%0,%1,%2,%3}, {%4,%5,%6,%7}, {%8,%9}, {%0,%1,%2,%3};"
        : "+f"(c[0]), "+f"(c[1]), "+f"(c[2]), "+f"(c[3])
        : "r"(a[0]), "r"(a[1]), "r"(a[2]), "r"(a[3]), "r"(b[0]), "r"(b[1]));
}
__device__ __forceinline__ uint32_t pk16(__nv_bfloat16 a, __nv_bfloat16 b) {
    __nv_bfloat162 t;
    t.x = a; t.y = b;
    return *reinterpret_cast<uint32_t*>(&t);
}
__device__ __forceinline__ float2 bf2f(uint32_t u) {
    __nv_bfloat162 t = *reinterpret_cast<__nv_bfloat162*>(&u);
    return make_float2(__bfloat162float(t.x), __bfloat162float(t.y));
}
__device__ __forceinline__ void split2(float v0, float v1, uint32_t& h, uint32_t& l) {
    __nv_bfloat16 h0 = __float2bfloat16(v0), h1 = __float2bfloat16(v1);
    h = pk16(h0, h1);
    l = pk16(__float2bfloat16(v0 - __bfloat162float(h0)),
             __float2bfloat16(v1 - __bfloat162float(h1)));
}

// ---------------- fused x-transpose + start conv -> stream planes [q][32] ----------
__global__ void __launch_bounds__(256) start_fused(const float* __restrict__ x,
                                                   const float* __restrict__ w,
                                                   __nv_bfloat16* __restrict__ XH,
                                                   __nv_bfloat16* __restrict__ XL)
{
    __shared__ float xs[5][8][256];
    __shared__ float ws[32][5];
    int tid = threadIdx.x;
    int t0 = blockIdx.x << 3;
    if (tid < 160) ws[tid / 5][tid % 5] = w[tid];
#pragma unroll
    for (int l = 0; l < 40; l++) {
        int idx = tid + (l << 8);       // 10240 floats
        int t = idx & 7;
        int rem = idx >> 3;
        int i = rem % 5;
        int b = rem / 5;
        xs[i][t][b] = x[b * 6400 + i * 1280 + t0 + t];
    }
    __syncthreads();
#pragma unroll
    for (int j = 0; j < 8; j++) {
        float xv[5];
#pragma unroll
        for (int i = 0; i < 5; i++) xv[i] = xs[i][j][tid];
        long q = (long)(t0 + j) * 256 + tid;
        uint32_t hw[16], lw[16];
#pragma unroll
        for (int c2 = 0; c2 < 16; c2++) {
            float a0 = 0.f, a1 = 0.f;
#pragma unroll
            for (int i = 0; i < 5; i++) {
                a0 += ws[2 * c2][i] * xv[i];
                a1 += ws[2 * c2 + 1][i] * xv[i];
            }
            split2(a0, a1, hw[c2], lw[c2]);
        }
#pragma unroll
        for (int u = 0; u < 4; u++) {
            *(float4*)((char*)XH + q * 64 + u * 16) = ((float4*)hw)[u];
            *(float4*)((char*)XL + q * 64 + u * 16) = ((float4*)lw)[u];
        }
    }
}

// ---------------- weight prep for skip/end1 ----------------
__global__ void prepw_kernel(const float* __restrict__ sw, const float* __restrict__ e1,
                             __nv_bfloat16* __restrict__ wt)
{
    int idx = blockIdx.x * 256 + threadIdx.x;
    if (idx < 49152) {
        int m = idx / 192, k = idx - m * 192;
        float v = sw[(k >> 5) * 8192 + m * 32 + (k & 31)];
        __nv_bfloat16 h = __float2bfloat16(v);
        wt[idx] = h;
        wt[49152 + idx] = __float2bfloat16(v - __bfloat162float(h));
    } else if (idx < 81920) {
        int i2 = idx - 49152;
        float v = e1[i2];
        __nv_bfloat16 h = __float2bfloat16(v);
        wt[98304 + i2] = h;
        wt[131072 + i2] = __float2bfloat16(v - __bfloat162float(h));
    }
}

// ---------------- per-layer weight prep + end2 weights ----------------
__global__ void prepl_kernel(const float* __restrict__ fw, const float* __restrict__ gw,
                             const float* __restrict__ rw, __nv_bfloat16* __restrict__ wl,
                             const float* __restrict__ e2,
                             __nv_bfloat16* __restrict__ e2H, __nv_bfloat16* __restrict__ e2L)
{
    int idx = blockIdx.x * 256 + threadIdx.x;
    if (idx < 24576) {
        int lay = idx >> 12;
        int r = idx & 4095;
        int m = r >> 6, k = r & 63;
        const float* src = ((m < 32) ? fw : gw) + lay * 2048 + (m & 31) * 64 + (k & 31) * 2 + (k >> 5);
        float v = *src;
        __nv_bfloat16 h = __float2bfloat16(v);
        wl[lay * 10240 + r] = h;
        wl[lay * 10240 + 4096 + r] = __float2bfloat16(v - __bfloat162float(h));
    } else if (idx < 30720) {
        int j = idx - 24576;
        int lay = j >> 10;
        int r = j & 1023;
        float v = rw[lay * 1024 + r];
        __nv_bfloat16 h = __float2bfloat16(v);
        wl[lay * 10240 + 8192 + r] = h;
        wl[lay * 10240 + 9216 + r] = __float2bfloat16(v - __bfloat162float(h));
    } else if (idx < 34816) {
        int i2 = idx - 30720;
        float v = e2[i2];
        __nv_bfloat16 h = __float2bfloat16(v);
        e2H[i2] = h;
        e2L[i2] = __float2bfloat16(v - __bfloat162float(h));
    }
}

// ---------------- fc1 weight prep: [m][c*317+t] -> bf16 hi/lo [m][t*32+c] ----------
__global__ void prepfc_kernel(const float* __restrict__ w1,
                              __nv_bfloat16* __restrict__ WH, __nv_bfloat16* __restrict__ WL)
{
    __shared__ float S[32][33];
    int m = blockIdx.y;
    int t0 = blockIdx.x << 5;
    int a = threadIdx.x & 31;
    int b8 = threadIdx.x >> 5;
#pragma unroll
    for (int l = 0; l < 4; l++) {
        int c = b8 + (l << 3);
        int t = t0 + a;
        S[c][a] = (t < 317) ? w1[m * 10144 + c * 317 + t] : 0.f;
    }
    __syncthreads();
#pragma unroll
    for (int l = 0; l < 4; l++) {
        int tt = b8 + (l << 3);
        int t = t0 + tt;
        if (t < 317) {
            float v = S[a][tt];
            __nv_bfloat16 h = __float2bfloat16(v);
            WH[m * 10144 + t * 32 + a] = h;
            WL[m * 10144 + t * 32 + a] = __float2bfloat16(v - __bfloat162float(h));
        }
    }
}

// ---------------- fused layer via mma.sync (128-row, 2 CTA/SM) ----------
__device__ __forceinline__ float fast_gate(float f, float g)
{
    float ef = __expf(f + f);
    float th = 1.f - __fdividef(2.f, ef + 1.f);
    float sg = __fdividef(1.f, 1.f + __expf(-g));
    return th * sg;
}

#define L_OFF_X  0
#define L_XPL    18432
#define L_OFF_W  36864
#define L_WPL    9216
#define L_OFF_WR 55296
#define L_WRPL   2560
#define L_OFF_H  60416
#define L_HPL    10240
#define L_OFF_R  36864          // overlay on W/WR (dead after stage-2 sync)
#define L_RPL    10240
#define L_SMEM   80896          // 2 CTAs/SM

__global__ void __launch_bounds__(256, 2) layer_mma(
    const __nv_bfloat16* __restrict__ XH, const __nv_bfloat16* __restrict__ XL,
    const __nv_bfloat16* __restrict__ wlay,
    __nv_bfloat16* __restrict__ gtH, __nv_bfloat16* __restrict__ gtL,
    __nv_bfloat16* __restrict__ RoutH, __nv_bfloat16* __restrict__ RoutL,
    int nr, int s, int off, int lay64, int writeRes)
{
    extern __shared__ char sm[];
    uint32_t sb = s2u(sm);
    int tid = threadIdx.x;
    int q0 = blockIdx.x << 7;

#pragma unroll
    for (int l = 0; l < 8; l++) {
        int idx = tid + (l << 8);
        int plane = idx >> 10;
        int r = (idx >> 3) & 127;
        int seg = idx & 7;
        int tap = seg >> 2;
        int qa = q0 + r - s + (tap ? nr : 0);
        char* dst = sm + L_OFF_X + plane * L_XPL + r * 144 + seg * 16;
        if (!tap && qa < 0) {
            *(float4*)dst = make_float4(0.f, 0.f, 0.f, 0.f);
        } else {
            const __nv_bfloat16* src = (plane ? XL : XH) + (long)qa * 32 + ((seg & 3) << 3);
            *(float4*)dst = *(const float4*)src;
        }
    }
#pragma unroll
    for (int l = 0; l < 4; l++) {
        int idx = tid + (l << 8);
        int plane = idx >> 9;
        int r = (idx >> 3) & 63;
        int cc = idx & 7;
        *(float4*)(sm + L_OFF_W + plane * L_WPL + r * 144 + cc * 16) =
            *(const float4*)(wlay + plane * 4096 + r * 64 + cc * 8);
    }
    {
        int idx = tid;
        int plane = idx >> 7;
        int r = (idx >> 2) & 31;
        int cc = idx & 3;
        *(float4*)(sm + L_OFF_WR + plane * L_WRPL + r * 80 + cc * 16) =
            *(const float4*)(wlay + 8192 + plane * 1024 + r * 32 + cc * 8);
    }
    __syncthreads();

    int warp = tid >> 5, lane = tid & 31;
    int warp_q = (warp & 3) << 5;
    int g = warp >> 2;
    int arow = lane & 15, acol = (lane >> 4) << 3;
    int brow = lane & 7, bcol = ((lane >> 3) & 1) << 3;

    float acc[2][4][4];
#pragma unroll
    for (int pt = 0; pt < 2; pt++)
#pragma unroll
        for (int nt = 0; nt < 4; nt++)
#pragma unroll
            for (int j = 0; j < 4; j++) acc[pt][nt][j] = 0.f;

#pragma unroll
    for (int kc = 0; kc < 4; kc++) {
        uint32_t aH[2][4], aL[2][4], bH[4][2], bL[4][2];
#pragma unroll
        for (int pt = 0; pt < 2; pt++) {
            uint32_t o = L_OFF_X + (uint32_t)((warp_q + (pt << 4) + arow) * 144 + (((kc << 4) + acol) << 1));
            ldm_x4(aH[pt], sb + o);
            ldm_x4(aL[pt], sb + L_XPL + o);
        }
#pragma unroll
        for (int nt = 0; nt < 4; nt++) {
            int msm = (nt < 2) ? (g * 16 + nt * 8) : (32 + g * 16 + (nt - 2) * 8);
            uint32_t o = L_OFF_W + (uint32_t)((msm + brow) * 144 + (((kc << 4) + bcol) << 1));
            ldm_x2(bH[nt], sb + o);
            ldm_x2(bL[nt], sb + L_WPL + o);
        }
#pragma unroll
        for (int pt = 0; pt < 2; pt++)
#pragma unroll
            for (int nt = 0; nt < 4; nt++) {
                mma16816(acc[pt][nt], aH[pt], bH[nt]);
                mma16816(acc[pt][nt], aL[pt], bH[nt]);
                mma16816(acc[pt][nt], aH[pt], bL[nt]);
            }
    }

#pragma unroll
    for (int pt = 0; pt < 2; pt++)
#pragma unroll
        for (int nt = 0; nt < 2; nt++)
#pragma unroll
            for (int jh = 0; jh < 2; jh++) {
                float F0 = acc[pt][nt][jh * 2], F1 = acc[pt][nt][jh * 2 + 1];
                float G0 = acc[pt][nt + 2][jh * 2], G1 = acc[pt][nt + 2][jh * 2 + 1];
                float h0 = fast_gate(F0, G0);
                float h1 = fast_gate(F1, G1);
                int q = warp_q + (pt << 4) + (lane >> 2) + (jh << 3);
                int c0 = g * 16 + nt * 8 + ((lane & 3) << 1);
                uint32_t hw, lw;
                split2(h0, h1, hw, lw);
                *(uint32_t*)(sm + L_OFF_H + q * 80 + c0 * 2) = hw;
                *(uint32_t*)(sm + L_OFF_H + L_HPL + q * 80 + c0 * 2) = lw;
            }
    __syncthreads();

#pragma unroll
    for (int l = 0; l < 4; l++) {
        int idx = tid + (l << 8);
        int plane = idx >> 9;
        int r = (idx >> 2) & 127;
        int cc = idx & 3;
        int pg = q0 + r - off;
        if (pg >= 0) {
            float4 v = *(float4*)(sm + L_OFF_H + plane * L_HPL + r * 80 + cc * 16);
            char* d = (char*)(plane ? gtL : gtH) + (long)pg * 384 + lay64 + cc * 16;
            *(float4*)d = v;
        }
    }

    if (writeRes) {
        float acc2[2][2][4];
#pragma unroll
        for (int pt = 0; pt < 2; pt++)
#pragma unroll
            for (int nt = 0; nt < 2; nt++)
#pragma unroll
                for (int j = 0; j < 4; j++) acc2[pt][nt][j] = 0.f;

#pragma unroll
        for (int kc = 0; kc < 2; kc++) {
            uint32_t aH[2][4], aL[2][4], bH[2][2], bL[2][2];
#pragma unroll
            for (int pt = 0; pt < 2; pt++) {
                uint32_t o = L_OFF_H + (uint32_t)((warp_q + (pt << 4) + arow) * 80 + (((kc << 4) + acol) << 1));
                ldm_x4(aH[pt], sb + o);
                ldm_x4(aL[pt], sb + L_HPL + o);
            }
#pragma unroll
            for (int nt = 0; nt < 2; nt++) {
                uint32_t o = L_OFF_WR + (uint32_t)((g * 16 + nt * 8 + brow) * 80 + (((kc << 4) + bcol) << 1));
                ldm_x2(bH[nt], sb + o);
                ldm_x2(bL[nt], sb + L_WRPL + o);
            }
#pragma unroll
            for (int pt = 0; pt < 2; pt++)
#pragma unroll
                for (int nt = 0; nt < 2; nt++) {
                    mma16816(acc2[pt][nt], aH[pt], bH[nt]);
                    mma16816(acc2[pt][nt], aL[pt], bH[nt]);
                    mma16816(acc2[pt][nt], aH[pt], bL[nt]);
                }
        }
        __syncthreads();   // all W/WR reads complete before R overlays them

#pragma unroll
        for (int pt = 0; pt < 2; pt++)
#pragma unroll
            for (int nt = 0; nt < 2; nt++)
#pragma unroll
                for (int jh = 0; jh < 2; jh++) {
                    int q = warp_q + (pt << 4) + (lane >> 2) + (jh << 3);
                    int c0 = g * 16 + nt * 8 + ((lane & 3) << 1);
                    const __nv_bfloat16* xh = (const __nv_bfloat16*)(sm + L_OFF_X + q * 144 + (32 + c0) * 2);
                    const __nv_bfloat16* xl = (const __nv_bfloat16*)(sm + L_OFF_X + L_XPL + q * 144 + (32 + c0) * 2);
                    float xb0 = __bfloat162float(xh[0]) + __bfloat162float(xl[0]);
                    float xb1 = __bfloat162float(xh[1]) + __bfloat162float(xl[1]);
                    float v0 = acc2[pt][nt][jh * 2] + xb0;
                    float v1 = acc2[pt][nt][jh * 2 + 1] + xb1;
                    uint32_t hw, lw;
                    split2(v0, v1, hw, lw);
                    *(uint32_t*)(sm + L_OFF_R + q * 80 + c0 * 2) = hw;
                    *(uint32_t*)(sm + L_OFF_R + L_RPL + q * 80 + c0 * 2) = lw;
                }
        __syncthreads();

#pragma unroll
        for (int l = 0; l < 4; l++) {
            int idx = tid + (l << 8);
            int plane = idx >> 9;
            int r = (idx >> 2) & 127;
            int cc = idx & 3;
            float4 v = *(float4*)(sm + L_OFF_R + plane * L_RPL + r * 80 + cc * 16);
            __nv_bfloat16* d = (plane ? RoutL : RoutH) + (long)(q0 + r) * 32 + cc * 8;
            *(float4*)d = v;
        }
    }
}

// ---------------- fused skip+end1 megakernel (double-buffered) ----------------
// Stage A buffers: buf0 @0 (SB 20KB + SW 40KB), buf1 @61440 (inside S region, dead then)
// Stage B buffers: 2 x 20KB W buffers @20480 / @40960 (old SW region)
// S: 61440..196608 (2 planes x 128 rows x 528B)
#define MG_SBPL   10240
#define MG_SWPL   20480
#define MG_OFF_S  61440
#define MG_SPL    67584
#define MG_SMEM   196608

__global__ void __launch_bounds__(256, 1) mega_gemm(
    const __nv_bfloat16* __restrict__ gtH, const __nv_bfloat16* __restrict__ gtL,
    const __nv_bfloat16* __restrict__ wskH, const __nv_bfloat16* __restrict__ wskL,
    const __nv_bfloat16* __restrict__ we1H, const __nv_bfloat16* __restrict__ we1L,
    const float* __restrict__ bias,
    __nv_bfloat16* __restrict__ y1H, __nv_bfloat16* __restrict__ y1L)
{
    extern __shared__ char sm[];
    uint32_t sb = s2u(sm);
    int tid = threadIdx.x;
    int warp = tid >> 5, lane = tid & 31;
    int p0 = blockIdx.x << 7;
    int warp_p = (warp & 1) << 6;
    int warp_mA = (warp >> 1) << 6;
    int warp_mB = (warp >> 1) << 5;
    int arow = lane & 15, acol = (lane >> 4) << 3;
    int brow = lane & 7, bcol = ((lane >> 3) & 1) << 3;
    int prow = lane >> 2, mcol = (lane & 3) << 1;

    // ---- stage A: double-buffered over 6 K-chunks of 32 ----
    float acc[4][8][4];
#pragma unroll
    for (int pt = 0; pt < 4; pt++)
#pragma unroll
        for (int nt = 0; nt < 8; nt++)
#pragma unroll
            for (int j = 0; j < 4; j++) acc[pt][nt][j] = 0.f;

    // loader: SB (gt tile) + SW (wsk tile) for chunk kc into buffer at base
    auto loadA = [&](int kc, uint32_t base) {
#pragma unroll
        for (int l = 0; l < 4; l++) {
            int idx = tid + (l << 8);
            int plane = idx >> 9;
            int r = (idx >> 2) & 127;
            int c = idx & 3;
            *(float4*)(sm + base + plane * MG_SBPL + r * 80 + c * 16) =
                *(const float4*)((plane ? gtL : gtH) + (long)(p0 + r) * 192 + kc * 32 + c * 8);
        }
#pragma unroll
        for (int l = 0; l < 8; l++) {
            int idx = tid + (l << 8);
            int plane = idx >> 10;
            int r = (idx >> 2) & 255;
            int c = idx & 3;
            *(float4*)(sm + base + 20480 + plane * MG_SWPL + r * 80 + c * 16) =
                *(const float4*)((plane ? wskL : wskH) + (long)r * 192 + kc * 32 + c * 8);
        }
    };

    loadA(0, 0);
    __syncthreads();
    for (int kc = 0; kc < 6; kc++) {
        uint32_t bcur = (kc & 1) ? 61440u : 0u;
        uint32_t bnxt = (kc & 1) ? 0u : 61440u;
        if (kc < 5) loadA(kc + 1, bnxt);
#pragma unroll
        for (int ks = 0; ks < 2; ks++) {
            uint32_t aH[4][4], aL[4][4], bH[8][2], bL[8][2];
#pragma unroll
            for (int pt = 0; pt < 4; pt++) {
                uint32_t o = bcur + (uint32_t)((warp_p + (pt << 4) + arow) * 80 + (((ks << 4) + acol) << 1));
                ldm_x4(aH[pt], sb + o);
                ldm_x4(aL[pt], sb + MG_SBPL + o);
            }
#pragma unroll
            for (int nt = 0; nt < 8; nt++) {
                uint32_t o = bcur + 20480 + (uint32_t)((warp_mA + (nt << 3) + brow) * 80 + (((ks << 4) + bcol) << 1));
                ldm_x2(bH[nt], sb + o);
                ldm_x2(bL[nt], sb + MG_SWPL + o);
            }
#pragma unroll
            for (int pt = 0; pt < 4; pt++)
#pragma unroll
                for (int nt = 0; nt < 8; nt++) {
                    mma16816(acc[pt][nt], aH[pt], bH[nt]);
                    mma16816(acc[pt][nt], aL[pt], bH[nt]);
                    mma16816(acc[pt][nt], aH[pt], bL[nt]);
                }
        }
        __syncthreads();
    }

    // epilogue A: relu + split -> S smem (overlaps buf1; safe after final sync)
#pragma unroll
    for (int pt = 0; pt < 4; pt++)
#pragma unroll
        for (int half = 0; half < 2; half++) {
            int pl = warp_p + (pt << 4) + prow + (half << 3);
#pragma unroll
            for (int nt = 0; nt < 8; nt++) {
                float v0 = fmaxf(acc[pt][nt][half * 2], 0.f);
                float v1 = fmaxf(acc[pt][nt][half * 2 + 1], 0.f);
                int m = warp_mA + (nt << 3) + mcol;
                uint32_t hw, lw;
                split2(v0, v1, hw, lw);
                *(uint32_t*)(sm + MG_OFF_S + pl * 528 + m * 2) = hw;
                *(uint32_t*)(sm + MG_OFF_S + MG_SPL + pl * 528 + m * 2) = lw;
            }
        }

    // ---- stage B: 8 chunks of 32 K-cols, double-buffered weights ----
    float acc2[4][4][4];
#pragma unroll
    for (int pt = 0; pt < 4; pt++)
#pragma unroll
        for (int nt = 0; nt < 4; nt++)
#pragma unroll
            for (int j = 0; j < 4; j++) acc2[pt][nt][j] = 0.f;

    auto loadB = [&](int kc, uint32_t base) {
#pragma unroll
        for (int l = 0; l < 4; l++) {
            int idx = tid + (l << 8);
            int plane = idx >> 9;
            int r = (idx >> 2) & 127;
            int c = idx & 3;
            *(float4*)(sm + base + plane * MG_SBPL + r * 80 + c * 16) =
                *(const float4*)((plane ? we1L : we1H) + (long)r * 256 + kc * 32 + c * 8);
        }
    };

    loadB(0, 20480);
    __syncthreads();    // also orders epilogue-A S writes before stage-B S reads
    for (int kc = 0; kc < 8; kc++) {
        uint32_t wcur = 20480u + ((kc & 1) ? 20480u : 0u);
        uint32_t wnxt = 20480u + ((kc & 1) ? 0u : 20480u);
        if (kc < 7) loadB(kc + 1, wnxt);
#pragma unroll
        for (int ks = 0; ks < 2; ks++) {
            uint32_t aH[4][4], aL[4][4], bH[4][2], bL[4][2];
#pragma unroll
            for (int pt = 0; pt < 4; pt++) {
                uint32_t o = MG_OFF_S + (uint32_t)((warp_p + (pt << 4) + arow) * 528 + (((kc << 5) + (ks << 4) + acol) << 1));
                ldm_x4(aH[pt], sb + o);
                ldm_x4(aL[pt], sb + MG_SPL + o);
            }
#pragma unroll
            for (int nt = 0; nt < 4; nt++) {
                uint32_t o = wcur + (uint32_t)((warp_mB + (nt << 3) + brow) * 80 + (((ks << 4) + bcol) << 1));
                ldm_x2(bH[nt], sb + o);
                ldm_x2(bL[nt], sb + MG_SBPL + o);
            }
#pragma unroll
            for (int pt = 0; pt < 4; pt++)
#pragma unroll
                for (int nt = 0; nt < 4; nt++) {
                    mma16816(acc2[pt][nt], aH[pt], bH[nt]);
                    mma16816(acc2[pt][nt], aL[pt], bH[nt]);
                    mma16816(acc2[pt][nt], aH[pt], bL[nt]);
                }
        }
        __syncthreads();
    }

    // epilogue B: +bias, relu, split -> y1 pairs
#pragma unroll
    for (int pt = 0; pt < 4; pt++)
#pragma unroll
        for (int half = 0; half < 2; half++) {
            int p = p0 + warp_p + (pt << 4) + prow + (half << 3);
#pragma unroll
            for (int nt = 0; nt < 4; nt++) {
                int m = warp_mB + (nt << 3) + mcol;
                float v0 = fmaxf(acc2[pt][nt][half * 2] + __ldg(&bias[m]), 0.f);
                float v1 = fmaxf(acc2[pt][nt][half * 2 + 1] + __ldg(&bias[m + 1]), 0.f);
                uint32_t hw, lw;
                split2(v0, v1, hw, lw);
                *(uint32_t*)((char*)y1H + (long)p * 256 + m * 2) = hw;
                *(uint32_t*)((char*)y1L + (long)p * 256 + m * 2) = lw;
            }
        }
}

// ---------------- fused pool1 + end2 (mma) ----------------
#define E2_OFF_A 0
#define E2_APL   69632
#define E2_OFF_W 139264
#define E2_WPL   8704
#define E2_SMEM  156672

__global__ void __launch_bounds__(256, 1) end2_mma(
    const __nv_bfloat16* __restrict__ y1H, const __nv_bfloat16* __restrict__ y1L,
    const __nv_bfloat16* __restrict__ we2H, const __nv_bfloat16* __restrict__ we2L,
    const float* __restrict__ bias,
    __nv_bfloat16* __restrict__ y2H, __nv_bfloat16* __restrict__ y2L)
{
    extern __shared__ char sm[];
    uint32_t sb = s2u(sm);
    int tid = threadIdx.x;
    int tq = blockIdx.x;

#pragma unroll
    for (int l = 0; l < 16; l++) {
        int idx = tid + (l << 8);
        int r = idx >> 4, c8 = idx & 15;
        long e = ((long)(2 * tq) * 256 + r) * 128 + (c8 << 3);
        float4 h0 = *(const float4*)(y1H + e);
        float4 h1 = *(const float4*)(y1H + e + 32768);
        float4 h2 = *(const float4*)(y1H + e + 65536);
        float4 l0 = *(const float4*)(y1L + e);
        float4 l1 = *(const float4*)(y1L + e + 32768);
        float4 l2 = *(const float4*)(y1L + e + 65536);
        uint32_t oh[4], ol[4];
#pragma unroll
        for (int w = 0; w < 4; w++) {
            float2 a0 = bf2f(((uint32_t*)&h0)[w]);
            float2 b0 = bf2f(((uint32_t*)&l0)[w]);
            float2 a1 = bf2f(((uint32_t*)&h1)[w]);
            float2 b1 = bf2f(((uint32_t*)&l1)[w]);
            float2 a2 = bf2f(((uint32_t*)&h2)[w]);
            float2 b2 = bf2f(((uint32_t*)&l2)[w]);
            float vx = fmaxf(fmaxf(a0.x + b0.x, a1.x + b1.x), a2.x + b2.x);
            float vy = fmaxf(fmaxf(a0.y + b0.y, a1.y + b1.y), a2.y + b2.y);
            split2(vx, vy, oh[w], ol[w]);
        }
        *(float4*)(sm + E2_OFF_A + r * 272 + c8 * 16) = *(float4*)oh;
        *(float4*)(sm + E2_OFF_A + E2_APL + r * 272 + c8 * 16) = *(float4*)ol;
    }
#pragma unroll
    for (int l = 0; l < 4; l++) {
        int idx = tid + (l << 8);
        int plane = idx >> 9;
        int r = (idx >> 4) & 31;
        int c = idx & 15;
        *(float4*)(sm + E2_OFF_W + plane * E2_WPL + r * 272 + c * 16) =
            *(const float4*)((plane ? we2L : we2H) + r * 128 + c * 8);
    }
    __syncthreads();

    int warp = tid >> 5, lane = tid & 31;
    int warp_p = warp << 5;
    int arow = lane & 15, acol = (lane >> 4) << 3;
    int brow = lane & 7, bcol = ((lane >> 3) & 1) << 3;
    int prow = lane >> 2, mcol = (lane & 3) << 1;

    float acc[2][4][4];
#pragma unroll
    for (int pt = 0; pt < 2; pt++)
#pragma unroll
        for (int nt = 0; nt < 4; nt++)
#pragma unroll
            for (int j = 0; j < 4; j++) acc[pt][nt][j] = 0.f;

#pragma unroll
    for (int ks = 0; ks < 8; ks++) {
        uint32_t aH[2][4], aL[2][4], bH[4][2], bL[4][2];
#pragma unroll
        for (int pt = 0; pt < 2; pt++) {
            uint32_t o = E2_OFF_A + (uint32_t)((warp_p + (pt << 4) + arow) * 272 + (((ks << 4) + acol) << 1));
            ldm_x4(aH[pt], sb + o);
            ldm_x4(aL[pt], sb + E2_APL + o);
        }
#pragma unroll
        for (int nt = 0; nt < 4; nt++) {
            uint32_t o = E2_OFF_W + (uint32_t)(((nt << 3) + brow) * 272 + (((ks << 4) + bcol) << 1));
            ldm_x2(bH[nt], sb + o);
            ldm_x2(bL[nt], sb + E2_WPL + o);
        }
#pragma unroll
        for (int pt = 0; pt < 2; pt++)
#pragma unroll
            for (int nt = 0; nt < 4; nt++) {
                mma16816(acc[pt][nt], aH[pt], bH[nt]);
                mma16816(acc[pt][nt], aL[pt], bH[nt]);
                mma16816(acc[pt][nt], aH[pt], bL[nt]);
            }
    }

#pragma unroll
    for (int pt = 0; pt < 2; pt++)
#pragma unroll
        for (int half = 0; half < 2; half++) {
            long pp = (long)tq * 256 + warp_p + (pt << 4) + prow + (half << 3);
#pragma unroll
            for (int nt = 0; nt < 4; nt++) {
                int m = (nt << 3) + mcol;
                float v0 = fmaxf(acc[pt][nt][half * 2] + __ldg(&bias[m]), 0.f);
                float v1 = fmaxf(acc[pt][nt][half * 2 + 1] + __ldg(&bias[m + 1]), 0.f);
                uint32_t hw, lw;
                split2(v0, v1, hw, lw);
                *(uint32_t*)((char*)y2H + pp * 64 + m * 2) = hw;
                *(uint32_t*)((char*)y2L + pp * 64 + m * 2) = lw;
            }
        }
}

// ---------------- pool2 on bf16 pairs ----------------
__global__ void pool2_kernel(const __nv_bfloat16* __restrict__ y2H, const __nv_bfloat16* __restrict__ y2L,
                             __nv_bfloat16* __restrict__ p2H, __nv_bfloat16* __restrict__ p2L)
{
    int idx = blockIdx.x * 256 + threadIdx.x;
    if (idx >= 81152 * 16) return;
    int u = idx & 15;
    int ppp = idx >> 4;
    int b = ppp & 255, tq = ppp >> 8;
    const uint32_t* H = (const uint32_t*)y2H;
    const uint32_t* L = (const uint32_t*)y2L;
    long r0 = ((long)(2 * tq) * 256 + b) * 16 + u;
    float2 a0 = bf2f(H[r0]),        b0 = bf2f(L[r0]);
    float2 a1 = bf2f(H[r0 + 4096]), b1 = bf2f(L[r0 + 4096]);
    float2 a2 = bf2f(H[r0 + 8192]), b2 = bf2f(L[r0 + 8192]);
    float vx = fmaxf(fmaxf(a0.x + b0.x, a1.x + b1.x), a2.x + b2.x);
    float vy = fmaxf(fmaxf(a0.y + b0.y, a1.y + b1.y), a2.y + b2.y);
    uint32_t hw, lw;
    split2(vx, vy, hw, lw);
    ((uint32_t*)p2H)[(long)ppp * 16 + u] = hw;
    ((uint32_t*)p2L)[(long)ppp * 16 + u] = lw;
}

// ---------------- fc1 via mma: 2 t per iteration (K=64), dynamic smem ----------------
#define F1_APL 18432           // per-plane A: 128 rows x 144B
#define F1_OFF_W 36864
#define F1_SMEM 73728

__global__ void __launch_bounds__(256, 1) fc1_mma(
    const __nv_bfloat16* __restrict__ p2H, const __nv_bfloat16* __restrict__ p2L,
    const __nv_bfloat16* __restrict__ wH, const __nv_bfloat16* __restrict__ wL,
    float* __restrict__ part)
{
    extern __shared__ char sm[];
    uint32_t sb = s2u(sm);
    int tid = threadIdx.x;
    int b0 = blockIdx.x << 7, m0 = blockIdx.y << 7, z = blockIdx.z;
    int t1 = z * 40 + 40; if (t1 > 317) t1 = 317;

    int warp = tid >> 5, lane = tid & 31;
    int warp_p = (warp & 1) << 6;
    int warp_m = (warp >> 1) << 5;
    int arow = lane & 15, acol = (lane >> 4) << 3;
    int brow = lane & 7, bcol = ((lane >> 3) & 1) << 3;
    int prow = lane >> 2, mcol = (lane & 3) << 1;

    float acc[4][4][4];
#pragma unroll
    for (int pt = 0; pt < 4; pt++)
#pragma unroll
        for (int nt = 0; nt < 4; nt++)
#pragma unroll
            for (int j = 0; j < 4; j++) acc[pt][nt][j] = 0.f;

    for (int t = z * 40; t < t1; t += 2) {
        int hasT1 = (t + 1 < t1);
        __syncthreads();
#pragma unroll
        for (int l = 0; l < 8; l++) {
            int idx = tid + (l << 8);
            int plane = idx >> 10;
            int r = (idx >> 3) & 127;
            int c = idx & 7;
            int tt = t + (c >> 2);
            float4 v;
            if (c >= 4 && !hasT1) v = make_float4(0.f, 0.f, 0.f, 0.f);
            else v = *(const float4*)((plane ? p2L : p2H) + (long)(tt * 256 + b0 + r) * 32 + (c & 3) * 8);
            *(float4*)(sm + plane * F1_APL + r * 144 + c * 16) = v;
        }
#pragma unroll
        for (int l = 0; l < 8; l++) {
            int idx = tid + (l << 8);
            int plane = idx >> 10;
            int r = (idx >> 3) & 127;
            int c = idx & 7;
            float4 v;
            if (c >= 4 && !hasT1) v = make_float4(0.f, 0.f, 0.f, 0.f);
            else v = *(const float4*)((plane ? wL : wH) + (long)(m0 + r) * 10144 + t * 32 + c * 8);
            *(float4*)(sm + F1_OFF_W + plane * F1_APL + r * 144 + c * 16) = v;
        }
        __syncthreads();
#pragma unroll
        for (int ks = 0; ks < 4; ks++) {
            uint32_t aH[4][4], aL[4][4], bH[4][2], bL[4][2];
#pragma unroll
            for (int pt = 0; pt < 4; pt++) {
                uint32_t o = (uint32_t)((warp_p + (pt << 4) + arow) * 144 + (((ks << 4) + acol) << 1));
                ldm_x4(aH[pt], sb + o);
                ldm_x4(aL[pt], sb + F1_APL + o);
            }
#pragma unroll
            for (int nt = 0; nt < 4; nt++) {
                uint32_t o = F1_OFF_W + (uint32_t)((warp_m + (nt << 3) + brow) * 144 + (((ks << 4) + bcol) << 1));
                ldm_x2(bH[nt], sb + o);
                ldm_x2(bL[nt], sb + F1_APL + o);
            }
#pragma unroll
            for (int pt = 0; pt < 4; pt++)
#pragma unroll
                for (int nt = 0; nt < 4; nt++) {
                    mma16816(acc[pt][nt], aH[pt], bH[nt]);
                    mma16816(acc[pt][nt], aL[pt], bH[nt]);
                    mma16816(acc[pt][nt], aH[pt], bL[nt]);
                }
        }
    }

#pragma unroll
    for (int pt = 0; pt < 4; pt++)
#pragma unroll
        for (int half = 0; half < 2; half++) {
            int b = b0 + warp_p + (pt << 4) + prow + (half << 3);
#pragma unroll
            for (int nt = 0; nt < 4; nt++) {
                int m = m0 + warp_m + (nt << 3) + mcol;
                part[(long)z * 262144 + m * 256 + b] = acc[pt][nt][half * 2];
                part[(long)z * 262144 + (m + 1) * 256 + b] = acc[pt][nt][half * 2 + 1];
            }
        }
}

// ---------------- 64x64 fp32 GEMM with split-K (fc2 only) ----------------
template <class AL, class BL, class EP>
__global__ void __launch_bounds__(256) gemm64_kernel(int totKB, int splitKB, AL al, BL bl, EP ep)
{
    __shared__ float As[32][68];
    __shared__ float Bs[32][68];
    int mBase = blockIdx.y << 6;
    int pBase = blockIdx.x << 6;
    int kb0 = blockIdx.z * splitKB;
    int kb1 = kb0 + splitKB; if (kb1 > totKB) kb1 = totKB;
    int tid = threadIdx.x;
    int tx = tid & 15, ty = tid >> 4;
    float acc[4][4];
#pragma unroll
    for (int i = 0; i < 4; i++)
#pragma unroll
        for (int j = 0; j < 4; j++) acc[i][j] = 0.f;

    for (int kb = kb0; kb < kb1; kb++) {
        int k0 = kb << 5;
#pragma unroll
        for (int i = 0; i < 8; i++) {
            int idx = tid + (i << 8);
            int m = idx >> 5, k = idx & 31;
            As[k][m] = al(mBase + m, k0 + k);
        }
#pragma unroll
        for (int i = 0; i < 8; i++) {
            int idx = tid + (i << 8);
            int k = idx >> 6, p = idx & 63;
            Bs[k][p] = bl(k0 + k, pBase + p);
        }
        __syncthreads();
#pragma unroll
        for (int k = 0; k < 32; k++) {
            float4 a4 = *(const float4*)&As[k][ty << 2];
            float4 b4 = *(const float4*)&Bs[k][tx << 2];
            float a[4] = {a4.x, a4.y, a4.z, a4.w};
            float bb[4] = {b4.x, b4.y, b4.z, b4.w};
#pragma unroll
            for (int i = 0; i < 4; i++)
#pragma unroll
                for (int j = 0; j < 4; j++) acc[i][j] += a[i] * bb[j];
        }
        __syncthreads();
    }
#pragma unroll
    for (int i = 0; i < 4; i++) {
        int m = mBase + (ty << 2) + i;
#pragma unroll
        for (int j = 0; j < 4; j++) {
            int p = pBase + (tx << 2) + j;
            ep.store(m, p, acc[i][j]);
        }
    }
}

struct ALRowG {
    const float* A; int K, M;
    __device__ float operator()(int m, int k) const {
        return (m < M) ? A[m * K + k] : 0.f;
    }
};
struct BLRow {
    const float* B; int N;
    __device__ float operator()(int k, int p) const { return B[k * N + p]; }
};
struct EPPart {
    float* out; int Mstride;
    __device__ void store(int m, int p, float v) const {
        out[blockIdx.z * Mstride + m * 256 + p] = v;
    }
};

// ---------------- split-K reduce + bias + relu ----------------
__global__ void reduce_kernel(const float* __restrict__ part, const float* __restrict__ bias,
                              float* __restrict__ out, int S, int Mstride, int total)
{
    int idx = blockIdx.x * 256 + threadIdx.x;
    if (idx >= total) return;
    int m = idx >> 8;
    float s = 0.f;
    for (int z = 0; z < S; z++) s += part[z * Mstride + idx];
    out[idx] = fmaxf(s + bias[m], 0.f);
}

// ---------------- fc3 + softmax + argmax ----------------
__global__ void fc3_softmax_kernel(const float* __restrict__ F2, const float* __restrict__ W3,
                                   const float* __restrict__ B3, float* __restrict__ out)
{
    int b = threadIdx.x;
    float l0 = B3[0], l1 = B3[1];
    for (int k = 0; k < 256; k++) {
        float v = F2[k * 256 + b];
        l0 += W3[k] * v;
        l1 += W3[256 + k] * v;
    }
    out[2 * b] = l0;
    out[2 * b + 1] = l1;
    float mx = fmaxf(l0, l1);
    float e0 = __expf(l0 - mx), e1 = __expf(l1 - mx);
    float inv = 1.f / (e0 + e1);
    out[512 + 2 * b] = e0 * inv;
    out[512 + 2 * b + 1] = e1 * inv;
    out[1024 + b] = (l1 > l0) ? 1.f : 0.f;
}

// ---------------- host orchestration ----------------
extern "C" void kernel_launch(void* const* d_in, const int* in_sizes, int n_in,
                              void* d_out, int out_size)
{
    const float* x        = (const float*)d_in[0];
    const float* start_w  = (const float*)d_in[1];
    const float* filter_w = (const float*)d_in[2];
    const float* gate_w   = (const float*)d_in[3];
    const float* res_w    = (const float*)d_in[4];
    const float* skip_w   = (const float*)d_in[5];
    const float* end1_w   = (const float*)d_in[6];
    const float* end1_b   = (const float*)d_in[7];
    const float* end2_w   = (const float*)d_in[8];
    const float* end2_b   = (const float*)d_in[9];
    const float* fc_w1    = (const float*)d_in[10];
    const float* fc_b1    = (const float*)d_in[11];
    const float* fc_w2    = (const float*)d_in[12];
    const float* fc_b2    = (const float*)d_in[13];
    const float* fc_w3    = (const float*)d_in[14];
    const float* fc_b3    = (const float*)d_in[15];

    float *r1, *r2, *G, *skipbuf, *y1, *y2, *p2, *f1p, *f1, *f2;
    __nv_bfloat16 *wtc, *wl;
    cudaGetSymbolAddress((void**)&r1, g_r1);
    cudaGetSymbolAddress((void**)&r2, g_r2);
    cudaGetSymbolAddress((void**)&G, g_G);
    cudaGetSymbolAddress((void**)&skipbuf, g_skip);
    cudaGetSymbolAddress((void**)&y1, g_y1);
    cudaGetSymbolAddress((void**)&y2, g_y2);
    cudaGetSymbolAddress((void**)&p2, g_p2);
    cudaGetSymbolAddress((void**)&f1p, g_f1p);
    cudaGetSymbolAddress((void**)&f1, g_f1);
    cudaGetSymbolAddress((void**)&f2, g_f2);
    cudaGetSymbolAddress((void**)&wtc, g_wtc);
    cudaGetSymbolAddress((void**)&wl, g_wlay);

    __nv_bfloat16* gtH = (__nv_bfloat16*)G;
    __nv_bfloat16* gtL = gtH + (long)NP * 192;
    __nv_bfloat16* wskH = wtc;
    __nv_bfloat16* wskL = wtc + 49152;
    __nv_bfloat16* we1H = wtc + 98304;
    __nv_bfloat16* we1L = wtc + 131072;

    __nv_bfloat16* s1H = (__nv_bfloat16*)r1;
    __nv_bfloat16* s1L = s1H + 10485760;
    __nv_bfloat16* s2H = (__nv_bfloat16*)r2;
    __nv_bfloat16* s2L = s2H + 10485760;

    __nv_bfloat16* y1H = (__nv_bfloat16*)y1;
    __nv_bfloat16* y1L = y1H + (long)NP * 128;
    __nv_bfloat16* y2H = (__nv_bfloat16*)y2;
    __nv_bfloat16* y2L = y2H + (long)162560 * 32;
    __nv_bfloat16* p2H = (__nv_bfloat16*)p2;
    __nv_bfloat16* p2L = p2H + (long)81152 * 32;

    __nv_bfloat16* wf1H = (__nv_bfloat16*)skipbuf;
    __nv_bfloat16* wf1L = wf1H + 10387456;
    __nv_bfloat16* we2H = wf1L + 10387456;
    __nv_bfloat16* we2L = we2H + 4096;

    cudaFuncSetAttribute(layer_mma, cudaFuncAttributeMaxDynamicSharedMemorySize, L_SMEM);
    cudaFuncSetAttribute(mega_gemm, cudaFuncAttributeMaxDynamicSharedMemorySize, MG_SMEM);
    cudaFuncSetAttribute(end2_mma, cudaFuncAttributeMaxDynamicSharedMemorySize, E2_SMEM);
    cudaFuncSetAttribute(fc1_mma, cudaFuncAttributeMaxDynamicSharedMemorySize, F1_SMEM);

    // preps first
    prepw_kernel<<<320, 256>>>(skip_w, end1_w, wtc);
    prepl_kernel<<<136, 256>>>(filter_w, gate_w, res_w, wl, end2_w, we2H, we2L);
    {
        dim3 gp(10, 1024);
        prepfc_kernel<<<gp, 256>>>(fc_w1, wf1H, wf1L);
    }
    // fused transpose + start conv -> stream planes in r1
    start_fused<<<160, 256>>>(x, start_w, s1H, s1L);

    // layers (128 q-rows per block, 2 CTAs/SM)
    const int QQ[6]  = {327424, 327168, 326656, 326400, 326144, 325632};
    const int NR[6]  = {256, 512, 1024, 256, 512, 1024};
    const int SS[6]  = {0, 256, 512, 0, 256, 512};
    const int OFF[6] = {1792, 1536, 1024, 768, 512, 0};

    __nv_bfloat16 *curH = s1H, *curL = s1L, *nxtH = s2H, *nxtL = s2L;
    for (int i = 0; i < 6; i++) {
        int nblk = QQ[i] >> 7;
        layer_mma<<<nblk, 256, L_SMEM>>>(curH, curL, wl + i * 10240,
                                         gtH, gtL, nxtH, nxtL,
                                         NR[i], SS[i], OFF[i], i * 64, (i < 5) ? 1 : 0);
        __nv_bfloat16* t;
        t = curH; curH = nxtH; nxtH = t;
        t = curL; curL = nxtL; nxtL = t;
    }

    // fused skip + end1 -> y1 pairs (double-buffered)
    mega_gemm<<<NP / 128, 256, MG_SMEM>>>(gtH, gtL, wskH, wskL, we1H, we1L, end1_b, y1H, y1L);

    // fused pool1 + end2 -> y2 pairs
    end2_mma<<<635, 256, E2_SMEM>>>(y1H, y1L, we2H, we2L, end2_b, y2H, y2L);

    // pool2 -> p2 pairs
    pool2_kernel<<<(81152 * 16 + 255) / 256, 256>>>(y2H, y2L, p2H, p2L);

    // fc1 (mma, split-K=8, 2 t per iter) -> partials -> reduce(+bias,relu) -> f1 fp32
    {
        dim3 gg(2, 8, 8);
        fc1_mma<<<gg, 256, F1_SMEM>>>(p2H, p2L, wf1H, wf1L, f1p);
        int total = 1024 * 256;
        reduce_kernel<<<(total + 255) / 256, 256>>>(f1p, fc_b1, f1, 8, total, total);
    }
    // fc2: 256 x 1024 x 256, fp32 split-K=8 (reuses f1p for partials)
    {
        ALRowG al = {fc_w2, 1024, 256};
        BLRow bl = {f1, 256};
        EPPart ep = {f1p, 256 * 256};
        dim3 gg(4, 4, 8);
        gemm64_kernel<<<gg, 256>>>(32, 4, al, bl, ep);
        int total = 256 * 256;
        reduce_kernel<<<(total + 255) / 256, 256>>>(f1p, fc_b2, f2, 8, total, total);
    }
    // fc3 + softmax + argmax
    fc3_softmax_kernel<<<1, 256>>>(f2, fc_w3, fc_b3, (float*)d_out);
}

// round 16
// speedup vs baseline: 1.0146x; 1.0146x over previous
#include <cuda_runtime.h>
#include <cuda_bf16.h>
#include <math.h>
#include <stdint.h>

#define NP 325632   // 1272 * 256 : columns of the big GEMMs, p = t*256 + b

// ---------------- scratch (device globals; no allocation) ----------------
__device__ float g_r1[10485760];     // stream ping: bf16 planes XH/XL [q][32]
__device__ float g_r2[10485760];     // stream pong
__device__ float g_G[62521344];      // bf16 planes: GtH [NP][192], GtL [NP][192]
__device__ float g_skip[83361792];   // reused: wfc1H/L bf16 [1024][10144], we2H/L [32][128]
__device__ float g_y1[41680896];     // bf16 planes y1H/[NP][128], y1L
__device__ float g_y2[5201920];      // bf16 planes y2H/[162560][32], y2L
__device__ float g_p2[2596864];      // bf16 planes p2H/[81152][32], p2L
__device__ float g_f1p[2097152];     // split-K partials (fc1: 8x1024x256; fc2: 8x256x256)
__device__ float g_f1[262144];       // 1024 x 256
__device__ float g_f2[65536];        // 256 x 256
__device__ __nv_bfloat16 g_wtc[163840]; // wskH[49152] wskL[49152] we1H[32768] we1L[32768]
__device__ __nv_bfloat16 g_wlay[61440]; // per-layer: WfgH[4096] WfgL[4096] WrH[1024] WrL[1024]

// ================= mma.sync helpers (sm_80+ portable) =================
__device__ __forceinline__ uint32_t s2u(const void* p) {
    uint32_t a;
    asm("{ .reg .u64 t; cvta.to.shared.u64 t, %1; cvt.u32.u64 %0, t; }" : "=r"(a) : "l"(p));
    return a;
}
__device__ __forceinline__ void ldm_x4(uint32_t* r, uint32_t addr) {
    asm volatile("ldmatrix.sync.aligned.m8n8.x4.shared.b16 {%0,%1,%2,%3}, [%4];"
                 : "=r"(r[0]), "=r"(r[1]), "=r"(r[2]), "=r"(r[3]) : "r"(addr));
}
__device__ __forceinline__ void ldm_x2(uint32_t* r, uint32_t addr) {
    asm volatile("ldmatrix.sync.aligned.m8n8.x2.shared.b16 {%0,%1}, [%2];"
                 : "=r"(r[0]), "=r"(r[1]) : "r"(addr));
}
__device__ __forceinline__ void mma16816(float* c, const uint32_t* a, const uint32_t* b) {
    asm volatile(
        "mma.sync.aligned.m16n8k16.row.col.f32.bf16.bf16.f32 "
        "{%0,%1,%2,%3}, {%4,%5,%6,%7}, {%8,%9}, {%0,%1,%2,%3};"
        : "+f"(c[0]), "+f"(c[1]), "+f"(c[2]), "+f"(c[3])
        : "r"(a[0]), "r"(a[1]), "r"(a[2]), "r"(a[3]), "r"(b[0]), "r"(b[1]));
}
__device__ __forceinline__ uint32_t pk16(__nv_bfloat16 a, __nv_bfloat16 b) {
    __nv_bfloat162 t;
    t.x = a; t.y = b;
    return *reinterpret_cast<uint32_t*>(&t);
}
__device__ __forceinline__ float2 bf2f(uint32_t u) {
    __nv_bfloat162 t = *reinterpret_cast<__nv_bfloat162*>(&u);
    return make_float2(__bfloat162float(t.x), __bfloat162float(t.y));
}
__device__ __forceinline__ void split2(float v0, float v1, uint32_t& h, uint32_t& l) {
    __nv_bfloat16 h0 = __float2bfloat16(v0), h1 = __float2bfloat16(v1);
    h = pk16(h0, h1);
    l = pk16(__float2bfloat16(v0 - __bfloat162float(h0)),
             __float2bfloat16(v1 - __bfloat162float(h1)));
}

// ---------------- fused x-transpose + start conv (4 t per block) ----------
__global__ void __launch_bounds__(256) start_fused(const float* __restrict__ x,
                                                   const float* __restrict__ w,
                                                   __nv_bfloat16* __restrict__ XH,
                                                   __nv_bfloat16* __restrict__ XL)
{
    __shared__ float xs[5][4][256];
    __shared__ float ws[32][5];
    int tid = threadIdx.x;
    int t0 = blockIdx.x << 2;
    if (tid < 160) ws[tid / 5][tid % 5] = w[tid];
#pragma unroll
    for (int l = 0; l < 20; l++) {
        int idx = tid + (l << 8);       // 5120 floats
        int t = idx & 3;
        int rem = idx >> 2;
        int i = rem % 5;
        int b = rem / 5;
        xs[i][t][b] = x[b * 6400 + i * 1280 + t0 + t];
    }
    __syncthreads();
#pragma unroll
    for (int j = 0; j < 4; j++) {
        float xv[5];
#pragma unroll
        for (int i = 0; i < 5; i++) xv[i] = xs[i][j][tid];
        long q = (long)(t0 + j) * 256 + tid;
        uint32_t hw[16], lw[16];
#pragma unroll
        for (int c2 = 0; c2 < 16; c2++) {
            float a0 = 0.f, a1 = 0.f;
#pragma unroll
            for (int i = 0; i < 5; i++) {
                a0 += ws[2 * c2][i] * xv[i];
                a1 += ws[2 * c2 + 1][i] * xv[i];
            }
            split2(a0, a1, hw[c2], lw[c2]);
        }
#pragma unroll
        for (int u = 0; u < 4; u++) {
            *(float4*)((char*)XH + q * 64 + u * 16) = ((float4*)hw)[u];
            *(float4*)((char*)XL + q * 64 + u * 16) = ((float4*)lw)[u];
        }
    }
}

// ---------------- weight prep for skip/end1 ----------------
__global__ void prepw_kernel(const float* __restrict__ sw, const float* __restrict__ e1,
                             __nv_bfloat16* __restrict__ wt)
{
    int idx = blockIdx.x * 256 + threadIdx.x;
    if (idx < 49152) {
        int m = idx / 192, k = idx - m * 192;
        float v = sw[(k >> 5) * 8192 + m * 32 + (k & 31)];
        __nv_bfloat16 h = __float2bfloat16(v);
        wt[idx] = h;
        wt[49152 + idx] = __float2bfloat16(v - __bfloat162float(h));
    } else if (idx < 81920) {
        int i2 = idx - 49152;
        float v = e1[i2];
        __nv_bfloat16 h = __float2bfloat16(v);
        wt[98304 + i2] = h;
        wt[131072 + i2] = __float2bfloat16(v - __bfloat162float(h));
    }
}

// ---------------- per-layer weight prep + end2 weights ----------------
__global__ void prepl_kernel(const float* __restrict__ fw, const float* __restrict__ gw,
                             const float* __restrict__ rw, __nv_bfloat16* __restrict__ wl,
                             const float* __restrict__ e2,
                             __nv_bfloat16* __restrict__ e2H, __nv_bfloat16* __restrict__ e2L)
{
    int idx = blockIdx.x * 256 + threadIdx.x;
    if (idx < 24576) {
        int lay = idx >> 12;
        int r = idx & 4095;
        int m = r >> 6, k = r & 63;
        const float* src = ((m < 32) ? fw : gw) + lay * 2048 + (m & 31) * 64 + (k & 31) * 2 + (k >> 5);
        float v = *src;
        __nv_bfloat16 h = __float2bfloat16(v);
        wl[lay * 10240 + r] = h;
        wl[lay * 10240 + 4096 + r] = __float2bfloat16(v - __bfloat162float(h));
    } else if (idx < 30720) {
        int j = idx - 24576;
        int lay = j >> 10;
        int r = j & 1023;
        float v = rw[lay * 1024 + r];
        __nv_bfloat16 h = __float2bfloat16(v);
        wl[lay * 10240 + 8192 + r] = h;
        wl[lay * 10240 + 9216 + r] = __float2bfloat16(v - __bfloat162float(h));
    } else if (idx < 34816) {
        int i2 = idx - 30720;
        float v = e2[i2];
        __nv_bfloat16 h = __float2bfloat16(v);
        e2H[i2] = h;
        e2L[i2] = __float2bfloat16(v - __bfloat162float(h));
    }
}

// ---------------- fc1 weight prep v2: one block per m, smem-staged transpose -------
__global__ void prepfc_kernel(const float* __restrict__ w1,
                              __nv_bfloat16* __restrict__ WH, __nv_bfloat16* __restrict__ WL)
{
    __shared__ float S[10144];
    int m = blockIdx.x;
    for (int i = threadIdx.x; i < 10144; i += 256)
        S[i] = w1[m * 10144 + i];
    __syncthreads();
    for (int i = threadIdx.x; i < 10144; i += 256) {
        int t = i >> 5, c = i & 31;
        float v = S[c * 317 + t];
        __nv_bfloat16 h = __float2bfloat16(v);
        WH[m * 10144 + i] = h;
        WL[m * 10144 + i] = __float2bfloat16(v - __bfloat162float(h));
    }
}

// ---------------- fused layer via mma.sync (128-row, 2 CTA/SM) ----------
__device__ __forceinline__ float fast_gate(float f, float g)
{
    float ef = __expf(f + f);
    float th = 1.f - __fdividef(2.f, ef + 1.f);
    float sg = __fdividef(1.f, 1.f + __expf(-g));
    return th * sg;
}

#define L_OFF_X  0
#define L_XPL    18432
#define L_OFF_W  36864
#define L_WPL    9216
#define L_OFF_WR 55296
#define L_WRPL   2560
#define L_OFF_H  60416
#define L_HPL    10240
#define L_OFF_R  36864          // overlay on W/WR (dead after stage-2 sync)
#define L_RPL    10240
#define L_SMEM   80896          // 2 CTAs/SM

__global__ void __launch_bounds__(256, 2) layer_mma(
    const __nv_bfloat16* __restrict__ XH, const __nv_bfloat16* __restrict__ XL,
    const __nv_bfloat16* __restrict__ wlay,
    __nv_bfloat16* __restrict__ gtH, __nv_bfloat16* __restrict__ gtL,
    __nv_bfloat16* __restrict__ RoutH, __nv_bfloat16* __restrict__ RoutL,
    int nr, int s, int off, int lay64, int writeRes)
{
    extern __shared__ char sm[];
    uint32_t sb = s2u(sm);
    int tid = threadIdx.x;
    int q0 = blockIdx.x << 7;

#pragma unroll
    for (int l = 0; l < 8; l++) {
        int idx = tid + (l << 8);
        int plane = idx >> 10;
        int r = (idx >> 3) & 127;
        int seg = idx & 7;
        int tap = seg >> 2;
        int qa = q0 + r - s + (tap ? nr : 0);
        char* dst = sm + L_OFF_X + plane * L_XPL + r * 144 + seg * 16;
        if (!tap && qa < 0) {
            *(float4*)dst = make_float4(0.f, 0.f, 0.f, 0.f);
        } else {
            const __nv_bfloat16* src = (plane ? XL : XH) + (long)qa * 32 + ((seg & 3) << 3);
            *(float4*)dst = *(const float4*)src;
        }
    }
#pragma unroll
    for (int l = 0; l < 4; l++) {
        int idx = tid + (l << 8);
        int plane = idx >> 9;
        int r = (idx >> 3) & 63;
        int cc = idx & 7;
        *(float4*)(sm + L_OFF_W + plane * L_WPL + r * 144 + cc * 16) =
            *(const float4*)(wlay + plane * 4096 + r * 64 + cc * 8);
    }
    {
        int idx = tid;
        int plane = idx >> 7;
        int r = (idx >> 2) & 31;
        int cc = idx & 3;
        *(float4*)(sm + L_OFF_WR + plane * L_WRPL + r * 80 + cc * 16) =
            *(const float4*)(wlay + 8192 + plane * 1024 + r * 32 + cc * 8);
    }
    __syncthreads();

    int warp = tid >> 5, lane = tid & 31;
    int warp_q = (warp & 3) << 5;
    int g = warp >> 2;
    int arow = lane & 15, acol = (lane >> 4) << 3;
    int brow = lane & 7, bcol = ((lane >> 3) & 1) << 3;

    float acc[2][4][4];
#pragma unroll
    for (int pt = 0; pt < 2; pt++)
#pragma unroll
        for (int nt = 0; nt < 4; nt++)
#pragma unroll
            for (int j = 0; j < 4; j++) acc[pt][nt][j] = 0.f;

#pragma unroll
    for (int kc = 0; kc < 4; kc++) {
        uint32_t aH[2][4], aL[2][4], bH[4][2], bL[4][2];
#pragma unroll
        for (int pt = 0; pt < 2; pt++) {
            uint32_t o = L_OFF_X + (uint32_t)((warp_q + (pt << 4) + arow) * 144 + (((kc << 4) + acol) << 1));
            ldm_x4(aH[pt], sb + o);
            ldm_x4(aL[pt], sb + L_XPL + o);
        }
#pragma unroll
        for (int nt = 0; nt < 4; nt++) {
            int msm = (nt < 2) ? (g * 16 + nt * 8) : (32 + g * 16 + (nt - 2) * 8);
            uint32_t o = L_OFF_W + (uint32_t)((msm + brow) * 144 + (((kc << 4) + bcol) << 1));
            ldm_x2(bH[nt], sb + o);
            ldm_x2(bL[nt], sb + L_WPL + o);
        }
#pragma unroll
        for (int pt = 0; pt < 2; pt++)
#pragma unroll
            for (int nt = 0; nt < 4; nt++) {
                mma16816(acc[pt][nt], aH[pt], bH[nt]);
                mma16816(acc[pt][nt], aL[pt], bH[nt]);
                mma16816(acc[pt][nt], aH[pt], bL[nt]);
            }
    }

#pragma unroll
    for (int pt = 0; pt < 2; pt++)
#pragma unroll
        for (int nt = 0; nt < 2; nt++)
#pragma unroll
            for (int jh = 0; jh < 2; jh++) {
                float F0 = acc[pt][nt][jh * 2], F1 = acc[pt][nt][jh * 2 + 1];
                float G0 = acc[pt][nt + 2][jh * 2], G1 = acc[pt][nt + 2][jh * 2 + 1];
                float h0 = fast_gate(F0, G0);
                float h1 = fast_gate(F1, G1);
                int q = warp_q + (pt << 4) + (lane >> 2) + (jh << 3);
                int c0 = g * 16 + nt * 8 + ((lane & 3) << 1);
                uint32_t hw, lw;
                split2(h0, h1, hw, lw);
                *(uint32_t*)(sm + L_OFF_H + q * 80 + c0 * 2) = hw;
                *(uint32_t*)(sm + L_OFF_H + L_HPL + q * 80 + c0 * 2) = lw;
            }
    __syncthreads();

#pragma unroll
    for (int l = 0; l < 4; l++) {
        int idx = tid + (l << 8);
        int plane = idx >> 9;
        int r = (idx >> 2) & 127;
        int cc = idx & 3;
        int pg = q0 + r - off;
        if (pg >= 0) {
            float4 v = *(float4*)(sm + L_OFF_H + plane * L_HPL + r * 80 + cc * 16);
            char* d = (char*)(plane ? gtL : gtH) + (long)pg * 384 + lay64 + cc * 16;
            *(float4*)d = v;
        }
    }

    if (writeRes) {
        float acc2[2][2][4];
#pragma unroll
        for (int pt = 0; pt < 2; pt++)
#pragma unroll
            for (int nt = 0; nt < 2; nt++)
#pragma unroll
                for (int j = 0; j < 4; j++) acc2[pt][nt][j] = 0.f;

#pragma unroll
        for (int kc = 0; kc < 2; kc++) {
            uint32_t aH[2][4], aL[2][4], bH[2][2], bL[2][2];
#pragma unroll
            for (int pt = 0; pt < 2; pt++) {
                uint32_t o = L_OFF_H + (uint32_t)((warp_q + (pt << 4) + arow) * 80 + (((kc << 4) + acol) << 1));
                ldm_x4(aH[pt], sb + o);
                ldm_x4(aL[pt], sb + L_HPL + o);
            }
#pragma unroll
            for (int nt = 0; nt < 2; nt++) {
                uint32_t o = L_OFF_WR + (uint32_t)((g * 16 + nt * 8 + brow) * 80 + (((kc << 4) + bcol) << 1));
                ldm_x2(bH[nt], sb + o);
                ldm_x2(bL[nt], sb + L_WRPL + o);
            }
#pragma unroll
            for (int pt = 0; pt < 2; pt++)
#pragma unroll
                for (int nt = 0; nt < 2; nt++) {
                    mma16816(acc2[pt][nt], aH[pt], bH[nt]);
                    mma16816(acc2[pt][nt], aL[pt], bH[nt]);
                    mma16816(acc2[pt][nt], aH[pt], bL[nt]);
                }
        }
        __syncthreads();   // all W/WR reads complete before R overlays them

#pragma unroll
        for (int pt = 0; pt < 2; pt++)
#pragma unroll
            for (int nt = 0; nt < 2; nt++)
#pragma unroll
                for (int jh = 0; jh < 2; jh++) {
                    int q = warp_q + (pt << 4) + (lane >> 2) + (jh << 3);
                    int c0 = g * 16 + nt * 8 + ((lane & 3) << 1);
                    const __nv_bfloat16* xh = (const __nv_bfloat16*)(sm + L_OFF_X + q * 144 + (32 + c0) * 2);
                    const __nv_bfloat16* xl = (const __nv_bfloat16*)(sm + L_OFF_X + L_XPL + q * 144 + (32 + c0) * 2);
                    float xb0 = __bfloat162float(xh[0]) + __bfloat162float(xl[0]);
                    float xb1 = __bfloat162float(xh[1]) + __bfloat162float(xl[1]);
                    float v0 = acc2[pt][nt][jh * 2] + xb0;
                    float v1 = acc2[pt][nt][jh * 2 + 1] + xb1;
                    uint32_t hw, lw;
                    split2(v0, v1, hw, lw);
                    *(uint32_t*)(sm + L_OFF_R + q * 80 + c0 * 2) = hw;
                    *(uint32_t*)(sm + L_OFF_R + L_RPL + q * 80 + c0 * 2) = lw;
                }
        __syncthreads();

#pragma unroll
        for (int l = 0; l < 4; l++) {
            int idx = tid + (l << 8);
            int plane = idx >> 9;
            int r = (idx >> 2) & 127;
            int cc = idx & 3;
            float4 v = *(float4*)(sm + L_OFF_R + plane * L_RPL + r * 80 + cc * 16);
            __nv_bfloat16* d = (plane ? RoutL : RoutH) + (long)(q0 + r) * 32 + cc * 8;
            *(float4*)d = v;
        }
    }
}

// ---------------- fused skip+end1 megakernel (R14 single-buffered) ----------------
#define MG_OFF_SB 0
#define MG_SBPL   10240
#define MG_OFF_SW 20480
#define MG_SWPL   20480
#define MG_OFF_S  61440
#define MG_SPL    67584
#define MG_SMEM   196608

__global__ void __launch_bounds__(256, 1) mega_gemm(
    const __nv_bfloat16* __restrict__ gtH, const __nv_bfloat16* __restrict__ gtL,
    const __nv_bfloat16* __restrict__ wskH, const __nv_bfloat16* __restrict__ wskL,
    const __nv_bfloat16* __restrict__ we1H, const __nv_bfloat16* __restrict__ we1L,
    const float* __restrict__ bias,
    __nv_bfloat16* __restrict__ y1H, __nv_bfloat16* __restrict__ y1L)
{
    extern __shared__ char sm[];
    uint32_t sb = s2u(sm);
    int tid = threadIdx.x;
    int warp = tid >> 5, lane = tid & 31;
    int p0 = blockIdx.x << 7;
    int warp_p = (warp & 1) << 6;
    int warp_mA = (warp >> 1) << 6;
    int warp_mB = (warp >> 1) << 5;
    int arow = lane & 15, acol = (lane >> 4) << 3;
    int brow = lane & 7, bcol = ((lane >> 3) & 1) << 3;
    int prow = lane >> 2, mcol = (lane & 3) << 1;

    // ---- stage A ----
    float acc[4][8][4];
#pragma unroll
    for (int pt = 0; pt < 4; pt++)
#pragma unroll
        for (int nt = 0; nt < 8; nt++)
#pragma unroll
            for (int j = 0; j < 4; j++) acc[pt][nt][j] = 0.f;

    for (int kc = 0; kc < 6; kc++) {
        __syncthreads();
#pragma unroll
        for (int l = 0; l < 4; l++) {
            int idx = tid + (l << 8);
            int plane = idx >> 9;
            int r = (idx >> 2) & 127;
            int c = idx & 3;
            *(float4*)(sm + MG_OFF_SB + plane * MG_SBPL + r * 80 + c * 16) =
                *(const float4*)((plane ? gtL : gtH) + (long)(p0 + r) * 192 + kc * 32 + c * 8);
        }
#pragma unroll
        for (int l = 0; l < 8; l++) {
            int idx = tid + (l << 8);
            int plane = idx >> 10;
            int r = (idx >> 2) & 255;
            int c = idx & 3;
            *(float4*)(sm + MG_OFF_SW + plane * MG_SWPL + r * 80 + c * 16) =
                *(const float4*)((plane ? wskL : wskH) + (long)r * 192 + kc * 32 + c * 8);
        }
        __syncthreads();
#pragma unroll
        for (int ks = 0; ks < 2; ks++) {
            uint32_t aH[4][4], aL[4][4], bH[8][2], bL[8][2];
#pragma unroll
            for (int pt = 0; pt < 4; pt++) {
                uint32_t o = MG_OFF_SB + (uint32_t)((warp_p + (pt << 4) + arow) * 80 + (((ks << 4) + acol) << 1));
                ldm_x4(aH[pt], sb + o);
                ldm_x4(aL[pt], sb + MG_SBPL + o);
            }
#pragma unroll
            for (int nt = 0; nt < 8; nt++) {
                uint32_t o = MG_OFF_SW + (uint32_t)((warp_mA + (nt << 3) + brow) * 80 + (((ks << 4) + bcol) << 1));
                ldm_x2(bH[nt], sb + o);
                ldm_x2(bL[nt], sb + MG_SWPL + o);
            }
#pragma unroll
            for (int pt = 0; pt < 4; pt++)
#pragma unroll
                for (int nt = 0; nt < 8; nt++) {
                    mma16816(acc[pt][nt], aH[pt], bH[nt]);
                    mma16816(acc[pt][nt], aL[pt], bH[nt]);
                    mma16816(acc[pt][nt], aH[pt], bL[nt]);
                }
        }
    }

    // epilogue A: relu + split -> S smem
#pragma unroll
    for (int pt = 0; pt < 4; pt++)
#pragma unroll
        for (int half = 0; half < 2; half++) {
            int pl = warp_p + (pt << 4) + prow + (half << 3);
#pragma unroll
            for (int nt = 0; nt < 8; nt++) {
                float v0 = fmaxf(acc[pt][nt][half * 2], 0.f);
                float v1 = fmaxf(acc[pt][nt][half * 2 + 1], 0.f);
                int m = warp_mA + (nt << 3) + mcol;
                uint32_t hw, lw;
                split2(v0, v1, hw, lw);
                *(uint32_t*)(sm + MG_OFF_S + pl * 528 + m * 2) = hw;
                *(uint32_t*)(sm + MG_OFF_S + MG_SPL + pl * 528 + m * 2) = lw;
            }
        }
    __syncthreads();

    // ---- stage B (64 K-columns of we1 per chunk, pitch 160) ----
    float acc2[4][4][4];
#pragma unroll
    for (int pt = 0; pt < 4; pt++)
#pragma unroll
        for (int nt = 0; nt < 4; nt++)
#pragma unroll
            for (int j = 0; j < 4; j++) acc2[pt][nt][j] = 0.f;

    for (int kc2 = 0; kc2 < 4; kc2++) {
        __syncthreads();
#pragma unroll
        for (int l = 0; l < 8; l++) {
            int idx = tid + (l << 8);      // 2048 chunks: 2 planes x 128 rows x 8 chunks
            int plane = idx >> 10;
            int r = (idx >> 3) & 127;
            int c = idx & 7;
            *(float4*)(sm + MG_OFF_SW + plane * MG_SWPL + r * 160 + c * 16) =
                *(const float4*)((plane ? we1L : we1H) + (long)r * 256 + kc2 * 64 + c * 8);
        }
        __syncthreads();
#pragma unroll
        for (int ks = 0; ks < 4; ks++) {
            uint32_t aH[4][4], aL[4][4], bH[4][2], bL[4][2];
#pragma unroll
            for (int pt = 0; pt < 4; pt++) {
                uint32_t o = MG_OFF_S + (uint32_t)((warp_p + (pt << 4) + arow) * 528 + (((kc2 << 6) + (ks << 4) + acol) << 1));
                ldm_x4(aH[pt], sb + o);
                ldm_x4(aL[pt], sb + MG_SPL + o);
            }
#pragma unroll
            for (int nt = 0; nt < 4; nt++) {
                uint32_t o = MG_OFF_SW + (uint32_t)((warp_mB + (nt << 3) + brow) * 160 + (((ks << 4) + bcol) << 1));
                ldm_x2(bH[nt], sb + o);
                ldm_x2(bL[nt], sb + MG_SWPL + o);
            }
#pragma unroll
            for (int pt = 0; pt < 4; pt++)
#pragma unroll
                for (int nt = 0; nt < 4; nt++) {
                    mma16816(acc2[pt][nt], aH[pt], bH[nt]);
                    mma16816(acc2[pt][nt], aL[pt], bH[nt]);
                    mma16816(acc2[pt][nt], aH[pt], bL[nt]);
                }
        }
    }

    // epilogue B: +bias, relu, split -> y1 pairs
#pragma unroll
    for (int pt = 0; pt < 4; pt++)
#pragma unroll
        for (int half = 0; half < 2; half++) {
            int p = p0 + warp_p + (pt << 4) + prow + (half << 3);
#pragma unroll
            for (int nt = 0; nt < 4; nt++) {
                int m = warp_mB + (nt << 3) + mcol;
                float v0 = fmaxf(acc2[pt][nt][half * 2] + __ldg(&bias[m]), 0.f);
                float v1 = fmaxf(acc2[pt][nt][half * 2 + 1] + __ldg(&bias[m + 1]), 0.f);
                uint32_t hw, lw;
                split2(v0, v1, hw, lw);
                *(uint32_t*)((char*)y1H + (long)p * 256 + m * 2) = hw;
                *(uint32_t*)((char*)y1L + (long)p * 256 + m * 2) = lw;
            }
        }
}

// ---------------- fused pool1 + end2 (mma) ----------------
#define E2_OFF_A 0
#define E2_APL   69632
#define E2_OFF_W 139264
#define E2_WPL   8704
#define E2_SMEM  156672

__global__ void __launch_bounds__(256, 1) end2_mma(
    const __nv_bfloat16* __restrict__ y1H, const __nv_bfloat16* __restrict__ y1L,
    const __nv_bfloat16* __restrict__ we2H, const __nv_bfloat16* __restrict__ we2L,
    const float* __restrict__ bias,
    __nv_bfloat16* __restrict__ y2H, __nv_bfloat16* __restrict__ y2L)
{
    extern __shared__ char sm[];
    uint32_t sb = s2u(sm);
    int tid = threadIdx.x;
    int tq = blockIdx.x;

#pragma unroll
    for (int l = 0; l < 16; l++) {
        int idx = tid + (l << 8);
        int r = idx >> 4, c8 = idx & 15;
        long e = ((long)(2 * tq) * 256 + r) * 128 + (c8 << 3);
        float4 h0 = *(const float4*)(y1H + e);
        float4 h1 = *(const float4*)(y1H + e + 32768);
        float4 h2 = *(const float4*)(y1H + e + 65536);
        float4 l0 = *(const float4*)(y1L + e);
        float4 l1 = *(const float4*)(y1L + e + 32768);
        float4 l2 = *(const float4*)(y1L + e + 65536);
        uint32_t oh[4], ol[4];
#pragma unroll
        for (int w = 0; w < 4; w++) {
            float2 a0 = bf2f(((uint32_t*)&h0)[w]);
            float2 b0 = bf2f(((uint32_t*)&l0)[w]);
            float2 a1 = bf2f(((uint32_t*)&h1)[w]);
            float2 b1 = bf2f(((uint32_t*)&l1)[w]);
            float2 a2 = bf2f(((uint32_t*)&h2)[w]);
            float2 b2 = bf2f(((uint32_t*)&l2)[w]);
            float vx = fmaxf(fmaxf(a0.x + b0.x, a1.x + b1.x), a2.x + b2.x);
            float vy = fmaxf(fmaxf(a0.y + b0.y, a1.y + b1.y), a2.y + b2.y);
            split2(vx, vy, oh[w], ol[w]);
        }
        *(float4*)(sm + E2_OFF_A + r * 272 + c8 * 16) = *(float4*)oh;
        *(float4*)(sm + E2_OFF_A + E2_APL + r * 272 + c8 * 16) = *(float4*)ol;
    }
#pragma unroll
    for (int l = 0; l < 4; l++) {
        int idx = tid + (l << 8);
        int plane = idx >> 9;
        int r = (idx >> 4) & 31;
        int c = idx & 15;
        *(float4*)(sm + E2_OFF_W + plane * E2_WPL + r * 272 + c * 16) =
            *(const float4*)((plane ? we2L : we2H) + r * 128 + c * 8);
    }
    __syncthreads();

    int warp = tid >> 5, lane = tid & 31;
    int warp_p = warp << 5;
    int arow = lane & 15, acol = (lane >> 4) << 3;
    int brow = lane & 7, bcol = ((lane >> 3) & 1) << 3;
    int prow = lane >> 2, mcol = (lane & 3) << 1;

    float acc[2][4][4];
#pragma unroll
    for (int pt = 0; pt < 2; pt++)
#pragma unroll
        for (int nt = 0; nt < 4; nt++)
#pragma unroll
            for (int j = 0; j < 4; j++) acc[pt][nt][j] = 0.f;

#pragma unroll
    for (int ks = 0; ks < 8; ks++) {
        uint32_t aH[2][4], aL[2][4], bH[4][2], bL[4][2];
#pragma unroll
        for (int pt = 0; pt < 2; pt++) {
            uint32_t o = E2_OFF_A + (uint32_t)((warp_p + (pt << 4) + arow) * 272 + (((ks << 4) + acol) << 1));
            ldm_x4(aH[pt], sb + o);
            ldm_x4(aL[pt], sb + E2_APL + o);
        }
#pragma unroll
        for (int nt = 0; nt < 4; nt++) {
            uint32_t o = E2_OFF_W + (uint32_t)(((nt << 3) + brow) * 272 + (((ks << 4) + bcol) << 1));
            ldm_x2(bH[nt], sb + o);
            ldm_x2(bL[nt], sb + E2_WPL + o);
        }
#pragma unroll
        for (int pt = 0; pt < 2; pt++)
#pragma unroll
            for (int nt = 0; nt < 4; nt++) {
                mma16816(acc[pt][nt], aH[pt], bH[nt]);
                mma16816(acc[pt][nt], aL[pt], bH[nt]);
                mma16816(acc[pt][nt], aH[pt], bL[nt]);
            }
    }

#pragma unroll
    for (int pt = 0; pt < 2; pt++)
#pragma unroll
        for (int half = 0; half < 2; half++) {
            long pp = (long)tq * 256 + warp_p + (pt << 4) + prow + (half << 3);
#pragma unroll
            for (int nt = 0; nt < 4; nt++) {
                int m = (nt << 3) + mcol;
                float v0 = fmaxf(acc[pt][nt][half * 2] + __ldg(&bias[m]), 0.f);
                float v1 = fmaxf(acc[pt][nt][half * 2 + 1] + __ldg(&bias[m + 1]), 0.f);
                uint32_t hw, lw;
                split2(v0, v1, hw, lw);
                *(uint32_t*)((char*)y2H + pp * 64 + m * 2) = hw;
                *(uint32_t*)((char*)y2L + pp * 64 + m * 2) = lw;
            }
        }
}

// ---------------- pool2 on bf16 pairs ----------------
__global__ void pool2_kernel(const __nv_bfloat16* __restrict__ y2H, const __nv_bfloat16* __restrict__ y2L,
                             __nv_bfloat16* __restrict__ p2H, __nv_bfloat16* __restrict__ p2L)
{
    int idx = blockIdx.x * 256 + threadIdx.x;
    if (idx >= 81152 * 16) return;
    int u = idx & 15;
    int ppp = idx >> 4;
    int b = ppp & 255, tq = ppp >> 8;
    const uint32_t* H = (const uint32_t*)y2H;
    const uint32_t* L = (const uint32_t*)y2L;
    long r0 = ((long)(2 * tq) * 256 + b) * 16 + u;
    float2 a0 = bf2f(H[r0]),        b0 = bf2f(L[r0]);
    float2 a1 = bf2f(H[r0 + 4096]), b1 = bf2f(L[r0 + 4096]);
    float2 a2 = bf2f(H[r0 + 8192]), b2 = bf2f(L[r0 + 8192]);
    float vx = fmaxf(fmaxf(a0.x + b0.x, a1.x + b1.x), a2.x + b2.x);
    float vy = fmaxf(fmaxf(a0.y + b0.y, a1.y + b1.y), a2.y + b2.y);
    uint32_t hw, lw;
    split2(vx, vy, hw, lw);
    ((uint32_t*)p2H)[(long)ppp * 16 + u] = hw;
    ((uint32_t*)p2L)[(long)ppp * 16 + u] = lw;
}

// ---------------- fc1 via mma: 2 t per iteration (K=64), dynamic smem ----------------
#define F1_APL 18432           // per-plane A: 128 rows x 144B
#define F1_OFF_W 36864
#define F1_SMEM 73728

__global__ void __launch_bounds__(256, 1) fc1_mma(
    const __nv_bfloat16* __restrict__ p2H, const __nv_bfloat16* __restrict__ p2L,
    const __nv_bfloat16* __restrict__ wH, const __nv_bfloat16* __restrict__ wL,
    float* __restrict__ part)
{
    extern __shared__ char sm[];
    uint32_t sb = s2u(sm);
    int tid = threadIdx.x;
    int b0 = blockIdx.x << 7, m0 = blockIdx.y << 7, z = blockIdx.z;
    int t1 = z * 40 + 40; if (t1 > 317) t1 = 317;

    int warp = tid >> 5, lane = tid & 31;
    int warp_p = (warp & 1) << 6;
    int warp_m = (warp >> 1) << 5;
    int arow = lane & 15, acol = (lane >> 4) << 3;
    int brow = lane & 7, bcol = ((lane >> 3) & 1) << 3;
    int prow = lane >> 2, mcol = (lane & 3) << 1;

    float acc[4][4][4];
#pragma unroll
    for (int pt = 0; pt < 4; pt++)
#pragma unroll
        for (int nt = 0; nt < 4; nt++)
#pragma unroll
            for (int j = 0; j < 4; j++) acc[pt][nt][j] = 0.f;

    for (int t = z * 40; t < t1; t += 2) {
        int hasT1 = (t + 1 < t1);
        __syncthreads();
#pragma unroll
        for (int l = 0; l < 8; l++) {
            int idx = tid + (l << 8);
            int plane = idx >> 10;
            int r = (idx >> 3) & 127;
            int c = idx & 7;
            int tt = t + (c >> 2);
            float4 v;
            if (c >= 4 && !hasT1) v = make_float4(0.f, 0.f, 0.f, 0.f);
            else v = *(const float4*)((plane ? p2L : p2H) + (long)(tt * 256 + b0 + r) * 32 + (c & 3) * 8);
            *(float4*)(sm + plane * F1_APL + r * 144 + c * 16) = v;
        }
#pragma unroll
        for (int l = 0; l < 8; l++) {
            int idx = tid + (l << 8);
            int plane = idx >> 10;
            int r = (idx >> 3) & 127;
            int c = idx & 7;
            float4 v;
            if (c >= 4 && !hasT1) v = make_float4(0.f, 0.f, 0.f, 0.f);
            else v = *(const float4*)((plane ? wL : wH) + (long)(m0 + r) * 10144 + t * 32 + c * 8);
            *(float4*)(sm + F1_OFF_W + plane * F1_APL + r * 144 + c * 16) = v;
        }
        __syncthreads();
#pragma unroll
        for (int ks = 0; ks < 4; ks++) {
            uint32_t aH[4][4], aL[4][4], bH[4][2], bL[4][2];
#pragma unroll
            for (int pt = 0; pt < 4; pt++) {
                uint32_t o = (uint32_t)((warp_p + (pt << 4) + arow) * 144 + (((ks << 4) + acol) << 1));
                ldm_x4(aH[pt], sb + o);
                ldm_x4(aL[pt], sb + F1_APL + o);
            }
#pragma unroll
            for (int nt = 0; nt < 4; nt++) {
                uint32_t o = F1_OFF_W + (uint32_t)((warp_m + (nt << 3) + brow) * 144 + (((ks << 4) + bcol) << 1));
                ldm_x2(bH[nt], sb + o);
                ldm_x2(bL[nt], sb + F1_APL + o);
            }
#pragma unroll
            for (int pt = 0; pt < 4; pt++)
#pragma unroll
                for (int nt = 0; nt < 4; nt++) {
                    mma16816(acc[pt][nt], aH[pt], bH[nt]);
                    mma16816(acc[pt][nt], aL[pt], bH[nt]);
                    mma16816(acc[pt][nt], aH[pt], bL[nt]);
                }
        }
    }

#pragma unroll
    for (int pt = 0; pt < 4; pt++)
#pragma unroll
        for (int half = 0; half < 2; half++) {
            int b = b0 + warp_p + (pt << 4) + prow + (half << 3);
#pragma unroll
            for (int nt = 0; nt < 4; nt++) {
                int m = m0 + warp_m + (nt << 3) + mcol;
                part[(long)z * 262144 + m * 256 + b] = acc[pt][nt][half * 2];
                part[(long)z * 262144 + (m + 1) * 256 + b] = acc[pt][nt][half * 2 + 1];
            }
        }
}

// ---------------- 64x64 fp32 GEMM with split-K (fc2 only) ----------------
template <class AL, class BL, class EP>
__global__ void __launch_bounds__(256) gemm64_kernel(int totKB, int splitKB, AL al, BL bl, EP ep)
{
    __shared__ float As[32][68];
    __shared__ float Bs[32][68];
    int mBase = blockIdx.y << 6;
    int pBase = blockIdx.x << 6;
    int kb0 = blockIdx.z * splitKB;
    int kb1 = kb0 + splitKB; if (kb1 > totKB) kb1 = totKB;
    int tid = threadIdx.x;
    int tx = tid & 15, ty = tid >> 4;
    float acc[4][4];
#pragma unroll
    for (int i = 0; i < 4; i++)
#pragma unroll
        for (int j = 0; j < 4; j++) acc[i][j] = 0.f;

    for (int kb = kb0; kb < kb1; kb++) {
        int k0 = kb << 5;
#pragma unroll
        for (int i = 0; i < 8; i++) {
            int idx = tid + (i << 8);
            int m = idx >> 5, k = idx & 31;
            As[k][m] = al(mBase + m, k0 + k);
        }
#pragma unroll
        for (int i = 0; i < 8; i++) {
            int idx = tid + (i << 8);
            int k = idx >> 6, p = idx & 63;
            Bs[k][p] = bl(k0 + k, pBase + p);
        }
        __syncthreads();
#pragma unroll
        for (int k = 0; k < 32; k++) {
            float4 a4 = *(const float4*)&As[k][ty << 2];
            float4 b4 = *(const float4*)&Bs[k][tx << 2];
            float a[4] = {a4.x, a4.y, a4.z, a4.w};
            float bb[4] = {b4.x, b4.y, b4.z, b4.w};
#pragma unroll
            for (int i = 0; i < 4; i++)
#pragma unroll
                for (int j = 0; j < 4; j++) acc[i][j] += a[i] * bb[j];
        }
        __syncthreads();
    }
#pragma unroll
    for (int i = 0; i < 4; i++) {
        int m = mBase + (ty << 2) + i;
#pragma unroll
        for (int j = 0; j < 4; j++) {
            int p = pBase + (tx << 2) + j;
            ep.store(m, p, acc[i][j]);
        }
    }
}

struct ALRowG {
    const float* A; int K, M;
    __device__ float operator()(int m, int k) const {
        return (m < M) ? A[m * K + k] : 0.f;
    }
};
struct BLRow {
    const float* B; int N;
    __device__ float operator()(int k, int p) const { return B[k * N + p]; }
};
struct EPPart {
    float* out; int Mstride;
    __device__ void store(int m, int p, float v) const {
        out[blockIdx.z * Mstride + m * 256 + p] = v;
    }
};

// ---------------- split-K reduce + bias + relu ----------------
__global__ void reduce_kernel(const float* __restrict__ part, const float* __restrict__ bias,
                              float* __restrict__ out, int S, int Mstride, int total)
{
    int idx = blockIdx.x * 256 + threadIdx.x;
    if (idx >= total) return;
    int m = idx >> 8;
    float s = 0.f;
    for (int z = 0; z < S; z++) s += part[z * Mstride + idx];
    out[idx] = fmaxf(s + bias[m], 0.f);
}

// ---------------- fc3 + softmax + argmax ----------------
__global__ void fc3_softmax_kernel(const float* __restrict__ F2, const float* __restrict__ W3,
                                   const float* __restrict__ B3, float* __restrict__ out)
{
    int b = threadIdx.x;
    float l0 = B3[0], l1 = B3[1];
    for (int k = 0; k < 256; k++) {
        float v = F2[k * 256 + b];
        l0 += W3[k] * v;
        l1 += W3[256 + k] * v;
    }
    out[2 * b] = l0;
    out[2 * b + 1] = l1;
    float mx = fmaxf(l0, l1);
    float e0 = __expf(l0 - mx), e1 = __expf(l1 - mx);
    float inv = 1.f / (e0 + e1);
    out[512 + 2 * b] = e0 * inv;
    out[512 + 2 * b + 1] = e1 * inv;
    out[1024 + b] = (l1 > l0) ? 1.f : 0.f;
}

// ---------------- host orchestration ----------------
extern "C" void kernel_launch(void* const* d_in, const int* in_sizes, int n_in,
                              void* d_out, int out_size)
{
    const float* x        = (const float*)d_in[0];
    const float* start_w  = (const float*)d_in[1];
    const float* filter_w = (const float*)d_in[2];
    const float* gate_w   = (const float*)d_in[3];
    const float* res_w    = (const float*)d_in[4];
    const float* skip_w   = (const float*)d_in[5];
    const float* end1_w   = (const float*)d_in[6];
    const float* end1_b   = (const float*)d_in[7];
    const float* end2_w   = (const float*)d_in[8];
    const float* end2_b   = (const float*)d_in[9];
    const float* fc_w1    = (const float*)d_in[10];
    const float* fc_b1    = (const float*)d_in[11];
    const float* fc_w2    = (const float*)d_in[12];
    const float* fc_b2    = (const float*)d_in[13];
    const float* fc_w3    = (const float*)d_in[14];
    const float* fc_b3    = (const float*)d_in[15];

    float *r1, *r2, *G, *skipbuf, *y1, *y2, *p2, *f1p, *f1, *f2;
    __nv_bfloat16 *wtc, *wl;
    cudaGetSymbolAddress((void**)&r1, g_r1);
    cudaGetSymbolAddress((void**)&r2, g_r2);
    cudaGetSymbolAddress((void**)&G, g_G);
    cudaGetSymbolAddress((void**)&skipbuf, g_skip);
    cudaGetSymbolAddress((void**)&y1, g_y1);
    cudaGetSymbolAddress((void**)&y2, g_y2);
    cudaGetSymbolAddress((void**)&p2, g_p2);
    cudaGetSymbolAddress((void**)&f1p, g_f1p);
    cudaGetSymbolAddress((void**)&f1, g_f1);
    cudaGetSymbolAddress((void**)&f2, g_f2);
    cudaGetSymbolAddress((void**)&wtc, g_wtc);
    cudaGetSymbolAddress((void**)&wl, g_wlay);

    __nv_bfloat16* gtH = (__nv_bfloat16*)G;
    __nv_bfloat16* gtL = gtH + (long)NP * 192;
    __nv_bfloat16* wskH = wtc;
    __nv_bfloat16* wskL = wtc + 49152;
    __nv_bfloat16* we1H = wtc + 98304;
    __nv_bfloat16* we1L = wtc + 131072;

    __nv_bfloat16* s1H = (__nv_bfloat16*)r1;
    __nv_bfloat16* s1L = s1H + 10485760;
    __nv_bfloat16* s2H = (__nv_bfloat16*)r2;
    __nv_bfloat16* s2L = s2H + 10485760;

    __nv_bfloat16* y1H = (__nv_bfloat16*)y1;
    __nv_bfloat16* y1L = y1H + (long)NP * 128;
    __nv_bfloat16* y2H = (__nv_bfloat16*)y2;
    __nv_bfloat16* y2L = y2H + (long)162560 * 32;
    __nv_bfloat16* p2H = (__nv_bfloat16*)p2;
    __nv_bfloat16* p2L = p2H + (long)81152 * 32;

    __nv_bfloat16* wf1H = (__nv_bfloat16*)skipbuf;
    __nv_bfloat16* wf1L = wf1H + 10387456;
    __nv_bfloat16* we2H = wf1L + 10387456;
    __nv_bfloat16* we2L = we2H + 4096;

    cudaFuncSetAttribute(layer_mma, cudaFuncAttributeMaxDynamicSharedMemorySize, L_SMEM);
    cudaFuncSetAttribute(mega_gemm, cudaFuncAttributeMaxDynamicSharedMemorySize, MG_SMEM);
    cudaFuncSetAttribute(end2_mma, cudaFuncAttributeMaxDynamicSharedMemorySize, E2_SMEM);
    cudaFuncSetAttribute(fc1_mma, cudaFuncAttributeMaxDynamicSharedMemorySize, F1_SMEM);

    // preps first
    prepw_kernel<<<320, 256>>>(skip_w, end1_w, wtc);
    prepl_kernel<<<136, 256>>>(filter_w, gate_w, res_w, wl, end2_w, we2H, we2L);
    prepfc_kernel<<<1024, 256>>>(fc_w1, wf1H, wf1L);
    // fused transpose + start conv -> stream planes in r1
    start_fused<<<320, 256>>>(x, start_w, s1H, s1L);

    // layers (128 q-rows per block, 2 CTAs/SM)
    const int QQ[6]  = {327424, 327168, 326656, 326400, 326144, 325632};
    const int NR[6]  = {256, 512, 1024, 256, 512, 1024};
    const int SS[6]  = {0, 256, 512, 0, 256, 512};
    const int OFF[6] = {1792, 1536, 1024, 768, 512, 0};

    __nv_bfloat16 *curH = s1H, *curL = s1L, *nxtH = s2H, *nxtL = s2L;
    for (int i = 0; i < 6; i++) {
        int nblk = QQ[i] >> 7;
        layer_mma<<<nblk, 256, L_SMEM>>>(curH, curL, wl + i * 10240,
                                         gtH, gtL, nxtH, nxtL,
                                         NR[i], SS[i], OFF[i], i * 64, (i < 5) ? 1 : 0);
        __nv_bfloat16* t;
        t = curH; curH = nxtH; nxtH = t;
        t = curL; curL = nxtL; nxtL = t;
    }

    // fused skip + end1 -> y1 pairs
    mega_gemm<<<NP / 128, 256, MG_SMEM>>>(gtH, gtL, wskH, wskL, we1H, we1L, end1_b, y1H, y1L);

    // fused pool1 + end2 -> y2 pairs
    end2_mma<<<635, 256, E2_SMEM>>>(y1H, y1L, we2H, we2L, end2_b, y2H, y2L);

    // pool2 -> p2 pairs
    pool2_kernel<<<(81152 * 16 + 255) / 256, 256>>>(y2H, y2L, p2H, p2L);

    // fc1 (mma, split-K=8, 2 t per iter) -> partials -> reduce(+bias,relu) -> f1 fp32
    {
        dim3 gg(2, 8, 8);
        fc1_mma<<<gg, 256, F1_SMEM>>>(p2H, p2L, wf1H, wf1L, f1p);
        int total = 1024 * 256;
        reduce_kernel<<<(total + 255) / 256, 256>>>(f1p, fc_b1, f1, 8, total, total);
    }
    // fc2: 256 x 1024 x 256, fp32 split-K=8 (reuses f1p for partials)
    {
        ALRowG al = {fc_w2, 1024, 256};
        BLRow bl = {f1, 256};
        EPPart ep = {f1p, 256 * 256};
        dim3 gg(4, 4, 8);
        gemm64_kernel<<<gg, 256>>>(32, 4, al, bl, ep);
        int total = 256 * 256;
        reduce_kernel<<<(total + 255) / 256, 256>>>(f1p, fc_b2, f2, 8, total, total);
    }
    // fc3 + softmax + argmax
    fc3_softmax_kernel<<<1, 256>>>(f2, fc_w3, fc_b3, (float*)d_out);
}

// round 17
// speedup vs baseline: 1.0386x; 1.0237x over previous
#include <cuda_runtime.h>
#include <cuda_bf16.h>
#include <math.h>
#include <stdint.h>

#define NP 325632   // 1272 * 256 : columns of the big GEMMs, p = t*256 + b

// ---------------- scratch (device globals; no allocation) ----------------
__device__ float g_r1[10485760];     // stream ping: bf16 planes XH/XL [q][32]
__device__ float g_r2[10485760];     // stream pong
__device__ float g_G[62521344];      // bf16 planes: GtH [NP][192], GtL [NP][192]
__device__ float g_skip[83361792];   // reused: wfc1H/L bf16 [1024][10144], we2H/L [32][128]
__device__ float g_y1[41680896];     // bf16 planes y1H/[NP][128], y1L
__device__ float g_y2[5201920];      // bf16 planes y2H/[162560][32], y2L
__device__ float g_p2[2596864];      // bf16 planes p2H/[81152][32], p2L
__device__ float g_f1p[2097152];     // split-K partials (fc1: 8x1024x256; fc2: 8x256x256)
__device__ float g_f1[262144];       // 1024 x 256
__device__ float g_f2[65536];        // 256 x 256
__device__ __nv_bfloat16 g_wtc[163840]; // wskH[49152] wskL[49152] we1H[32768] we1L[32768]
__device__ __nv_bfloat16 g_wlay[61440]; // per-layer: WfgH[4096] WfgL[4096] WrH[1024] WrL[1024]

// ================= mma.sync helpers (sm_80+ portable) =================
__device__ __forceinline__ uint32_t s2u(const void* p) {
    uint32_t a;
    asm("{ .reg .u64 t; cvta.to.shared.u64 t, %1; cvt.u32.u64 %0, t; }" : "=r"(a) : "l"(p));
    return a;
}
__device__ __forceinline__ void ldm_x4(uint32_t* r, uint32_t addr) {
    asm volatile("ldmatrix.sync.aligned.m8n8.x4.shared.b16 {%0,%1,%2,%3}, [%4];"
                 : "=r"(r[0]), "=r"(r[1]), "=r"(r[2]), "=r"(r[3]) : "r"(addr));
}
__device__ __forceinline__ void ldm_x2(uint32_t* r, uint32_t addr) {
    asm volatile("ldmatrix.sync.aligned.m8n8.x2.shared.b16 {%0,%1}, [%2];"
                 : "=r"(r[0]), "=r"(r[1]) : "r"(addr));
}
__device__ __forceinline__ void mma16816(float* c, const uint32_t* a, const uint32_t* b) {
    asm volatile(
        "mma.sync.aligned.m16n8k16.row.col.f32.bf16.bf16.f32 "
        "{%0,%1,%2,%3}, {%4,%5,%6,%7}, {%8,%9}, {%0,%1,%2,%3};"
        : "+f"(c[0]), "+f"(c[1]), "+f"(c[2]), "+f"(c[3])
        : "r"(a[0]), "r"(a[1]), "r"(a[2]), "r"(a[3]), "r"(b[0]), "r"(b[1]));
}
__device__ __forceinline__ uint32_t pk16(__nv_bfloat16 a, __nv_bfloat16 b) {
    __nv_bfloat162 t;
    t.x = a; t.y = b;
    return *reinterpret_cast<uint32_t*>(&t);
}
__device__ __forceinline__ float2 bf2f(uint32_t u) {
    __nv_bfloat162 t = *reinterpret_cast<__nv_bfloat162*>(&u);
    return make_float2(__bfloat162float(t.x), __bfloat162float(t.y));
}
__device__ __forceinline__ void split2(float v0, float v1, uint32_t& h, uint32_t& l) {
    __nv_bfloat16 h0 = __float2bfloat16(v0), h1 = __float2bfloat16(v1);
    h = pk16(h0, h1);
    l = pk16(__float2bfloat16(v0 - __bfloat162float(h0)),
             __float2bfloat16(v1 - __bfloat162float(h1)));
}

// ---------------- fused x-transpose + start conv (4 t per block, low-reg) ----------
__global__ void __launch_bounds__(256, 2) start_fused(const float* __restrict__ x,
                                                      const float* __restrict__ w,
                                                      __nv_bfloat16* __restrict__ XH,
                                                      __nv_bfloat16* __restrict__ XL)
{
    __shared__ float xs[5][4][256];
    __shared__ float ws[32][5];
    int tid = threadIdx.x;
    int t0 = blockIdx.x << 2;
    if (tid < 160) ws[tid / 5][tid % 5] = w[tid];
#pragma unroll
    for (int l = 0; l < 20; l++) {
        int idx = tid + (l << 8);       // 5120 floats
        int t = idx & 3;
        int rem = idx >> 2;
        int i = rem % 5;
        int b = rem / 5;
        xs[i][t][b] = x[b * 6400 + i * 1280 + t0 + t];
    }
    __syncthreads();
#pragma unroll
    for (int j = 0; j < 4; j++) {
        float xv[5];
#pragma unroll
        for (int i = 0; i < 5; i++) xv[i] = xs[i][j][tid];
        long q = (long)(t0 + j) * 256 + tid;
#pragma unroll
        for (int u = 0; u < 4; u++) {
            uint32_t hw4[4], lw4[4];
#pragma unroll
            for (int c2l = 0; c2l < 4; c2l++) {
                int c2 = (u << 2) + c2l;
                float a0 = 0.f, a1 = 0.f;
#pragma unroll
                for (int i = 0; i < 5; i++) {
                    a0 += ws[2 * c2][i] * xv[i];
                    a1 += ws[2 * c2 + 1][i] * xv[i];
                }
                split2(a0, a1, hw4[c2l], lw4[c2l]);
            }
            *(float4*)((char*)XH + q * 64 + u * 16) = *(float4*)hw4;
            *(float4*)((char*)XL + q * 64 + u * 16) = *(float4*)lw4;
        }
    }
}

// ---------------- weight prep for skip/end1 ----------------
__global__ void prepw_kernel(const float* __restrict__ sw, const float* __restrict__ e1,
                             __nv_bfloat16* __restrict__ wt)
{
    int idx = blockIdx.x * 256 + threadIdx.x;
    if (idx < 49152) {
        int m = idx / 192, k = idx - m * 192;
        float v = sw[(k >> 5) * 8192 + m * 32 + (k & 31)];
        __nv_bfloat16 h = __float2bfloat16(v);
        wt[idx] = h;
        wt[49152 + idx] = __float2bfloat16(v - __bfloat162float(h));
    } else if (idx < 81920) {
        int i2 = idx - 49152;
        float v = e1[i2];
        __nv_bfloat16 h = __float2bfloat16(v);
        wt[98304 + i2] = h;
        wt[131072 + i2] = __float2bfloat16(v - __bfloat162float(h));
    }
}

// ---------------- per-layer weight prep + end2 weights ----------------
__global__ void prepl_kernel(const float* __restrict__ fw, const float* __restrict__ gw,
                             const float* __restrict__ rw, __nv_bfloat16* __restrict__ wl,
                             const float* __restrict__ e2,
                             __nv_bfloat16* __restrict__ e2H, __nv_bfloat16* __restrict__ e2L)
{
    int idx = blockIdx.x * 256 + threadIdx.x;
    if (idx < 24576) {
        int lay = idx >> 12;
        int r = idx & 4095;
        int m = r >> 6, k = r & 63;
        const float* src = ((m < 32) ? fw : gw) + lay * 2048 + (m & 31) * 64 + (k & 31) * 2 + (k >> 5);
        float v = *src;
        __nv_bfloat16 h = __float2bfloat16(v);
        wl[lay * 10240 + r] = h;
        wl[lay * 10240 + 4096 + r] = __float2bfloat16(v - __bfloat162float(h));
    } else if (idx < 30720) {
        int j = idx - 24576;
        int lay = j >> 10;
        int r = j & 1023;
        float v = rw[lay * 1024 + r];
        __nv_bfloat16 h = __float2bfloat16(v);
        wl[lay * 10240 + 8192 + r] = h;
        wl[lay * 10240 + 9216 + r] = __float2bfloat16(v - __bfloat162float(h));
    } else if (idx < 34816) {
        int i2 = idx - 30720;
        float v = e2[i2];
        __nv_bfloat16 h = __float2bfloat16(v);
        e2H[i2] = h;
        e2L[i2] = __float2bfloat16(v - __bfloat162float(h));
    }
}

// ---------------- fc1 weight prep: one block per m, smem-staged transpose -------
__global__ void prepfc_kernel(const float* __restrict__ w1,
                              __nv_bfloat16* __restrict__ WH, __nv_bfloat16* __restrict__ WL)
{
    __shared__ float S[10144];
    int m = blockIdx.x;
    for (int i = threadIdx.x; i < 10144; i += 256)
        S[i] = w1[m * 10144 + i];
    __syncthreads();
    for (int i = threadIdx.x; i < 10144; i += 256) {
        int t = i >> 5, c = i & 31;
        float v = S[c * 317 + t];
        __nv_bfloat16 h = __float2bfloat16(v);
        WH[m * 10144 + i] = h;
        WL[m * 10144 + i] = __float2bfloat16(v - __bfloat162float(h));
    }
}

// ---------------- fused layer via mma.sync (128-row, 2 CTA/SM) ----------
__device__ __forceinline__ float fast_gate(float f, float g)
{
    float ef = __expf(f + f);
    float th = 1.f - __fdividef(2.f, ef + 1.f);
    float sg = __fdividef(1.f, 1.f + __expf(-g));
    return th * sg;
}

#define L_OFF_X  0
#define L_XPL    18432
#define L_OFF_W  36864
#define L_WPL    9216
#define L_OFF_WR 55296
#define L_WRPL   2560
#define L_OFF_H  60416
#define L_HPL    10240
#define L_OFF_R  36864          // overlay on W/WR (dead after stage-2 sync)
#define L_RPL    10240
#define L_SMEM   80896          // 2 CTAs/SM

__global__ void __launch_bounds__(256, 2) layer_mma(
    const __nv_bfloat16* __restrict__ XH, const __nv_bfloat16* __restrict__ XL,
    const __nv_bfloat16* __restrict__ wlay,
    __nv_bfloat16* __restrict__ gtH, __nv_bfloat16* __restrict__ gtL,
    __nv_bfloat16* __restrict__ RoutH, __nv_bfloat16* __restrict__ RoutL,
    int nr, int s, int off, int lay64, int writeRes)
{
    extern __shared__ char sm[];
    uint32_t sb = s2u(sm);
    int tid = threadIdx.x;
    int q0 = blockIdx.x << 7;

#pragma unroll
    for (int l = 0; l < 8; l++) {
        int idx = tid + (l << 8);
        int plane = idx >> 10;
        int r = (idx >> 3) & 127;
        int seg = idx & 7;
        int tap = seg >> 2;
        int qa = q0 + r - s + (tap ? nr : 0);
        char* dst = sm + L_OFF_X + plane * L_XPL + r * 144 + seg * 16;
        if (!tap && qa < 0) {
            *(float4*)dst = make_float4(0.f, 0.f, 0.f, 0.f);
        } else {
            const __nv_bfloat16* src = (plane ? XL : XH) + (long)qa * 32 + ((seg & 3) << 3);
            *(float4*)dst = *(const float4*)src;
        }
    }
#pragma unroll
    for (int l = 0; l < 4; l++) {
        int idx = tid + (l << 8);
        int plane = idx >> 9;
        int r = (idx >> 3) & 63;
        int cc = idx & 7;
        *(float4*)(sm + L_OFF_W + plane * L_WPL + r * 144 + cc * 16) =
            *(const float4*)(wlay + plane * 4096 + r * 64 + cc * 8);
    }
    {
        int idx = tid;
        int plane = idx >> 7;
        int r = (idx >> 2) & 31;
        int cc = idx & 3;
        *(float4*)(sm + L_OFF_WR + plane * L_WRPL + r * 80 + cc * 16) =
            *(const float4*)(wlay + 8192 + plane * 1024 + r * 32 + cc * 8);
    }
    __syncthreads();

    int warp = tid >> 5, lane = tid & 31;
    int warp_q = (warp & 3) << 5;
    int g = warp >> 2;
    int arow = lane & 15, acol = (lane >> 4) << 3;
    int brow = lane & 7, bcol = ((lane >> 3) & 1) << 3;

    float acc[2][4][4];
#pragma unroll
    for (int pt = 0; pt < 2; pt++)
#pragma unroll
        for (int nt = 0; nt < 4; nt++)
#pragma unroll
            for (int j = 0; j < 4; j++) acc[pt][nt][j] = 0.f;

#pragma unroll
    for (int kc = 0; kc < 4; kc++) {
        uint32_t aH[2][4], aL[2][4], bH[4][2], bL[4][2];
#pragma unroll
        for (int pt = 0; pt < 2; pt++) {
            uint32_t o = L_OFF_X + (uint32_t)((warp_q + (pt << 4) + arow) * 144 + (((kc << 4) + acol) << 1));
            ldm_x4(aH[pt], sb + o);
            ldm_x4(aL[pt], sb + L_XPL + o);
        }
#pragma unroll
        for (int nt = 0; nt < 4; nt++) {
            int msm = (nt < 2) ? (g * 16 + nt * 8) : (32 + g * 16 + (nt - 2) * 8);
            uint32_t o = L_OFF_W + (uint32_t)((msm + brow) * 144 + (((kc << 4) + bcol) << 1));
            ldm_x2(bH[nt], sb + o);
            ldm_x2(bL[nt], sb + L_WPL + o);
        }
#pragma unroll
        for (int pt = 0; pt < 2; pt++)
#pragma unroll
            for (int nt = 0; nt < 4; nt++) {
                mma16816(acc[pt][nt], aH[pt], bH[nt]);
                mma16816(acc[pt][nt], aL[pt], bH[nt]);
                mma16816(acc[pt][nt], aH[pt], bL[nt]);
            }
    }

#pragma unroll
    for (int pt = 0; pt < 2; pt++)
#pragma unroll
        for (int nt = 0; nt < 2; nt++)
#pragma unroll
            for (int jh = 0; jh < 2; jh++) {
                float F0 = acc[pt][nt][jh * 2], F1 = acc[pt][nt][jh * 2 + 1];
                float G0 = acc[pt][nt + 2][jh * 2], G1 = acc[pt][nt + 2][jh * 2 + 1];
                float h0 = fast_gate(F0, G0);
                float h1 = fast_gate(F1, G1);
                int q = warp_q + (pt << 4) + (lane >> 2) + (jh << 3);
                int c0 = g * 16 + nt * 8 + ((lane & 3) << 1);
                uint32_t hw, lw;
                split2(h0, h1, hw, lw);
                *(uint32_t*)(sm + L_OFF_H + q * 80 + c0 * 2) = hw;
                *(uint32_t*)(sm + L_OFF_H + L_HPL + q * 80 + c0 * 2) = lw;
            }
    __syncthreads();

#pragma unroll
    for (int l = 0; l < 4; l++) {
        int idx = tid + (l << 8);
        int plane = idx >> 9;
        int r = (idx >> 2) & 127;
        int cc = idx & 3;
        int pg = q0 + r - off;
        if (pg >= 0) {
            float4 v = *(float4*)(sm + L_OFF_H + plane * L_HPL + r * 80 + cc * 16);
            char* d = (char*)(plane ? gtL : gtH) + (long)pg * 384 + lay64 + cc * 16;
            *(float4*)d = v;
        }
    }

    if (writeRes) {
        float acc2[2][2][4];
#pragma unroll
        for (int pt = 0; pt < 2; pt++)
#pragma unroll
            for (int nt = 0; nt < 2; nt++)
#pragma unroll
                for (int j = 0; j < 4; j++) acc2[pt][nt][j] = 0.f;

#pragma unroll
        for (int kc = 0; kc < 2; kc++) {
            uint32_t aH[2][4], aL[2][4], bH[2][2], bL[2][2];
#pragma unroll
            for (int pt = 0; pt < 2; pt++) {
                uint32_t o = L_OFF_H + (uint32_t)((warp_q + (pt << 4) + arow) * 80 + (((kc << 4) + acol) << 1));
                ldm_x4(aH[pt], sb + o);
                ldm_x4(aL[pt], sb + L_HPL + o);
            }
#pragma unroll
            for (int nt = 0; nt < 2; nt++) {
                uint32_t o = L_OFF_WR + (uint32_t)((g * 16 + nt * 8 + brow) * 80 + (((kc << 4) + bcol) << 1));
                ldm_x2(bH[nt], sb + o);
                ldm_x2(bL[nt], sb + L_WRPL + o);
            }
#pragma unroll
            for (int pt = 0; pt < 2; pt++)
#pragma unroll
                for (int nt = 0; nt < 2; nt++) {
                    mma16816(acc2[pt][nt], aH[pt], bH[nt]);
                    mma16816(acc2[pt][nt], aL[pt], bH[nt]);
                    mma16816(acc2[pt][nt], aH[pt], bL[nt]);
                }
        }
        __syncthreads();   // all W/WR reads complete before R overlays them

#pragma unroll
        for (int pt = 0; pt < 2; pt++)
#pragma unroll
            for (int nt = 0; nt < 2; nt++)
#pragma unroll
                for (int jh = 0; jh < 2; jh++) {
                    int q = warp_q + (pt << 4) + (lane >> 2) + (jh << 3);
                    int c0 = g * 16 + nt * 8 + ((lane & 3) << 1);
                    const __nv_bfloat16* xh = (const __nv_bfloat16*)(sm + L_OFF_X + q * 144 + (32 + c0) * 2);
                    const __nv_bfloat16* xl = (const __nv_bfloat16*)(sm + L_OFF_X + L_XPL + q * 144 + (32 + c0) * 2);
                    float xb0 = __bfloat162float(xh[0]) + __bfloat162float(xl[0]);
                    float xb1 = __bfloat162float(xh[1]) + __bfloat162float(xl[1]);
                    float v0 = acc2[pt][nt][jh * 2] + xb0;
                    float v1 = acc2[pt][nt][jh * 2 + 1] + xb1;
                    uint32_t hw, lw;
                    split2(v0, v1, hw, lw);
                    *(uint32_t*)(sm + L_OFF_R + q * 80 + c0 * 2) = hw;
                    *(uint32_t*)(sm + L_OFF_R + L_RPL + q * 80 + c0 * 2) = lw;
                }
        __syncthreads();

#pragma unroll
        for (int l = 0; l < 4; l++) {
            int idx = tid + (l << 8);
            int plane = idx >> 9;
            int r = (idx >> 2) & 127;
            int cc = idx & 3;
            float4 v = *(float4*)(sm + L_OFF_R + plane * L_RPL + r * 80 + cc * 16);
            __nv_bfloat16* d = (plane ? RoutL : RoutH) + (long)(q0 + r) * 32 + cc * 8;
            *(float4*)d = v;
        }
    }
}

// ---------------- fused skip+end1 megakernel (64-col chunks, low sync count) -------
// Stage A: SB @0 (2 planes x 128 x 144B), SW @36864 (2 planes x 256 x 144B)
// S overlays stage-A buffers @0 (2 planes x 128 x 528B = 135168)
// Stage B weights @135168 (2 planes x 128 x 144B)
#define MA_SB    0
#define MA_SBPL  18432
#define MA_SW    36864
#define MA_SWPL  36864
#define MG_OFF_S 0
#define MG_SPL   67584
#define MB_W     135168
#define MB_WPL   18432
#define MG_SMEM  196608

__global__ void __launch_bounds__(256, 1) mega_gemm(
    const __nv_bfloat16* __restrict__ gtH, const __nv_bfloat16* __restrict__ gtL,
    const __nv_bfloat16* __restrict__ wskH, const __nv_bfloat16* __restrict__ wskL,
    const __nv_bfloat16* __restrict__ we1H, const __nv_bfloat16* __restrict__ we1L,
    const float* __restrict__ bias,
    __nv_bfloat16* __restrict__ y1H, __nv_bfloat16* __restrict__ y1L)
{
    extern __shared__ char sm[];
    uint32_t sb = s2u(sm);
    int tid = threadIdx.x;
    int warp = tid >> 5, lane = tid & 31;
    int p0 = blockIdx.x << 7;
    int warp_p = (warp & 1) << 6;
    int warp_mA = (warp >> 1) << 6;
    int warp_mB = (warp >> 1) << 5;
    int arow = lane & 15, acol = (lane >> 4) << 3;
    int brow = lane & 7, bcol = ((lane >> 3) & 1) << 3;
    int prow = lane >> 2, mcol = (lane & 3) << 1;

    // ---- stage A: 3 chunks of 64 K-cols ----
    float acc[4][8][4];
#pragma unroll
    for (int pt = 0; pt < 4; pt++)
#pragma unroll
        for (int nt = 0; nt < 8; nt++)
#pragma unroll
            for (int j = 0; j < 4; j++) acc[pt][nt][j] = 0.f;

    for (int kc = 0; kc < 3; kc++) {
        if (kc) __syncthreads();
        // SB: 2048 chunks (2 planes x 128 rows x 8 c16)
#pragma unroll
        for (int l = 0; l < 8; l++) {
            int idx = tid + (l << 8);
            int plane = idx >> 10;
            int r = (idx >> 3) & 127;
            int c = idx & 7;
            *(float4*)(sm + MA_SB + plane * MA_SBPL + r * 144 + c * 16) =
                *(const float4*)((plane ? gtL : gtH) + (long)(p0 + r) * 192 + kc * 64 + c * 8);
        }
        // SW: 4096 chunks (2 planes x 256 rows x 8 c16)
#pragma unroll
        for (int l = 0; l < 16; l++) {
            int idx = tid + (l << 8);
            int plane = idx >> 11;
            int r = (idx >> 3) & 255;
            int c = idx & 7;
            *(float4*)(sm + MA_SW + plane * MA_SWPL + r * 144 + c * 16) =
                *(const float4*)((plane ? wskL : wskH) + (long)r * 192 + kc * 64 + c * 8);
        }
        __syncthreads();
#pragma unroll
        for (int ks = 0; ks < 4; ks++) {
            uint32_t aH[4][4], aL[4][4], bH[8][2], bL[8][2];
#pragma unroll
            for (int pt = 0; pt < 4; pt++) {
                uint32_t o = MA_SB + (uint32_t)((warp_p + (pt << 4) + arow) * 144 + (((ks << 4) + acol) << 1));
                ldm_x4(aH[pt], sb + o);
                ldm_x4(aL[pt], sb + MA_SBPL + o);
            }
#pragma unroll
            for (int nt = 0; nt < 8; nt++) {
                uint32_t o = MA_SW + (uint32_t)((warp_mA + (nt << 3) + brow) * 144 + (((ks << 4) + bcol) << 1));
                ldm_x2(bH[nt], sb + o);
                ldm_x2(bL[nt], sb + MA_SWPL + o);
            }
#pragma unroll
            for (int pt = 0; pt < 4; pt++)
#pragma unroll
                for (int nt = 0; nt < 8; nt++) {
                    mma16816(acc[pt][nt], aH[pt], bH[nt]);
                    mma16816(acc[pt][nt], aL[pt], bH[nt]);
                    mma16816(acc[pt][nt], aH[pt], bL[nt]);
                }
        }
    }
    __syncthreads();   // stage-A reads done before S overlays SB/SW

    // epilogue A: relu + split -> S smem (overlay)
#pragma unroll
    for (int pt = 0; pt < 4; pt++)
#pragma unroll
        for (int half = 0; half < 2; half++) {
            int pl = warp_p + (pt << 4) + prow + (half << 3);
#pragma unroll
            for (int nt = 0; nt < 8; nt++) {
                float v0 = fmaxf(acc[pt][nt][half * 2], 0.f);
                float v1 = fmaxf(acc[pt][nt][half * 2 + 1], 0.f);
                int m = warp_mA + (nt << 3) + mcol;
                uint32_t hw, lw;
                split2(v0, v1, hw, lw);
                *(uint32_t*)(sm + MG_OFF_S + pl * 528 + m * 2) = hw;
                *(uint32_t*)(sm + MG_OFF_S + MG_SPL + pl * 528 + m * 2) = lw;
            }
        }

    // ---- stage B: 4 chunks of 64 K-cols, weights @MB_W (disjoint from S) ----
    float acc2[4][4][4];
#pragma unroll
    for (int pt = 0; pt < 4; pt++)
#pragma unroll
        for (int nt = 0; nt < 4; nt++)
#pragma unroll
            for (int j = 0; j < 4; j++) acc2[pt][nt][j] = 0.f;

    for (int kc2 = 0; kc2 < 4; kc2++) {
        if (kc2) __syncthreads();
#pragma unroll
        for (int l = 0; l < 8; l++) {
            int idx = tid + (l << 8);      // 2048 chunks: 2 planes x 128 rows x 8 c16
            int plane = idx >> 10;
            int r = (idx >> 3) & 127;
            int c = idx & 7;
            *(float4*)(sm + MB_W + plane * MB_WPL + r * 144 + c * 16) =
                *(const float4*)((plane ? we1L : we1H) + (long)r * 256 + kc2 * 64 + c * 8);
        }
        __syncthreads();   // orders W load (and, for kc2=0, epilogue-A S writes) before reads
#pragma unroll
        for (int ks = 0; ks < 4; ks++) {
            uint32_t aH[4][4], aL[4][4], bH[4][2], bL[4][2];
#pragma unroll
            for (int pt = 0; pt < 4; pt++) {
                uint32_t o = MG_OFF_S + (uint32_t)((warp_p + (pt << 4) + arow) * 528 + (((kc2 << 6) + (ks << 4) + acol) << 1));
                ldm_x4(aH[pt], sb + o);
                ldm_x4(aL[pt], sb + MG_SPL + o);
            }
#pragma unroll
            for (int nt = 0; nt < 4; nt++) {
                uint32_t o = MB_W + (uint32_t)((warp_mB + (nt << 3) + brow) * 144 + (((ks << 4) + bcol) << 1));
                ldm_x2(bH[nt], sb + o);
                ldm_x2(bL[nt], sb + MB_WPL + o);
            }
#pragma unroll
            for (int pt = 0; pt < 4; pt++)
#pragma unroll
                for (int nt = 0; nt < 4; nt++) {
                    mma16816(acc2[pt][nt], aH[pt], bH[nt]);
                    mma16816(acc2[pt][nt], aL[pt], bH[nt]);
                    mma16816(acc2[pt][nt], aH[pt], bL[nt]);
                }
        }
    }

    // epilogue B: +bias, relu, split -> y1 pairs
#pragma unroll
    for (int pt = 0; pt < 4; pt++)
#pragma unroll
        for (int half = 0; half < 2; half++) {
            int p = p0 + warp_p + (pt << 4) + prow + (half << 3);
#pragma unroll
            for (int nt = 0; nt < 4; nt++) {
                int m = warp_mB + (nt << 3) + mcol;
                float v0 = fmaxf(acc2[pt][nt][half * 2] + __ldg(&bias[m]), 0.f);
                float v1 = fmaxf(acc2[pt][nt][half * 2 + 1] + __ldg(&bias[m + 1]), 0.f);
                uint32_t hw, lw;
                split2(v0, v1, hw, lw);
                *(uint32_t*)((char*)y1H + (long)p * 256 + m * 2) = hw;
                *(uint32_t*)((char*)y1L + (long)p * 256 + m * 2) = lw;
            }
        }
}

// ---------------- fused pool1 + end2 (mma) ----------------
#define E2_OFF_A 0
#define E2_APL   69632
#define E2_OFF_W 139264
#define E2_WPL   8704
#define E2_SMEM  156672

__global__ void __launch_bounds__(256, 1) end2_mma(
    const __nv_bfloat16* __restrict__ y1H, const __nv_bfloat16* __restrict__ y1L,
    const __nv_bfloat16* __restrict__ we2H, const __nv_bfloat16* __restrict__ we2L,
    const float* __restrict__ bias,
    __nv_bfloat16* __restrict__ y2H, __nv_bfloat16* __restrict__ y2L)
{
    extern __shared__ char sm[];
    uint32_t sb = s2u(sm);
    int tid = threadIdx.x;
    int tq = blockIdx.x;

#pragma unroll
    for (int l = 0; l < 16; l++) {
        int idx = tid + (l << 8);
        int r = idx >> 4, c8 = idx & 15;
        long e = ((long)(2 * tq) * 256 + r) * 128 + (c8 << 3);
        float4 h0 = *(const float4*)(y1H + e);
        float4 h1 = *(const float4*)(y1H + e + 32768);
        float4 h2 = *(const float4*)(y1H + e + 65536);
        float4 l0 = *(const float4*)(y1L + e);
        float4 l1 = *(const float4*)(y1L + e + 32768);
        float4 l2 = *(const float4*)(y1L + e + 65536);
        uint32_t oh[4], ol[4];
#pragma unroll
        for (int w = 0; w < 4; w++) {
            float2 a0 = bf2f(((uint32_t*)&h0)[w]);
            float2 b0 = bf2f(((uint32_t*)&l0)[w]);
            float2 a1 = bf2f(((uint32_t*)&h1)[w]);
            float2 b1 = bf2f(((uint32_t*)&l1)[w]);
            float2 a2 = bf2f(((uint32_t*)&h2)[w]);
            float2 b2 = bf2f(((uint32_t*)&l2)[w]);
            float vx = fmaxf(fmaxf(a0.x + b0.x, a1.x + b1.x), a2.x + b2.x);
            float vy = fmaxf(fmaxf(a0.y + b0.y, a1.y + b1.y), a2.y + b2.y);
            split2(vx, vy, oh[w], ol[w]);
        }
        *(float4*)(sm + E2_OFF_A + r * 272 + c8 * 16) = *(float4*)oh;
        *(float4*)(sm + E2_OFF_A + E2_APL + r * 272 + c8 * 16) = *(float4*)ol;
    }
#pragma unroll
    for (int l = 0; l < 4; l++) {
        int idx = tid + (l << 8);
        int plane = idx >> 9;
        int r = (idx >> 4) & 31;
        int c = idx & 15;
        *(float4*)(sm + E2_OFF_W + plane * E2_WPL + r * 272 + c * 16) =
            *(const float4*)((plane ? we2L : we2H) + r * 128 + c * 8);
    }
    __syncthreads();

    int warp = tid >> 5, lane = tid & 31;
    int warp_p = warp << 5;
    int arow = lane & 15, acol = (lane >> 4) << 3;
    int brow = lane & 7, bcol = ((lane >> 3) & 1) << 3;
    int prow = lane >> 2, mcol = (lane & 3) << 1;

    float acc[2][4][4];
#pragma unroll
    for (int pt = 0; pt < 2; pt++)
#pragma unroll
        for (int nt = 0; nt < 4; nt++)
#pragma unroll
            for (int j = 0; j < 4; j++) acc[pt][nt][j] = 0.f;

#pragma unroll
    for (int ks = 0; ks < 8; ks++) {
        uint32_t aH[2][4], aL[2][4], bH[4][2], bL[4][2];
#pragma unroll
        for (int pt = 0; pt < 2; pt++) {
            uint32_t o = E2_OFF_A + (uint32_t)((warp_p + (pt << 4) + arow) * 272 + (((ks << 4) + acol) << 1));
            ldm_x4(aH[pt], sb + o);
            ldm_x4(aL[pt], sb + E2_APL + o);
        }
#pragma unroll
        for (int nt = 0; nt < 4; nt++) {
            uint32_t o = E2_OFF_W + (uint32_t)(((nt << 3) + brow) * 272 + (((ks << 4) + bcol) << 1));
            ldm_x2(bH[nt], sb + o);
            ldm_x2(bL[nt], sb + E2_WPL + o);
        }
#pragma unroll
        for (int pt = 0; pt < 2; pt++)
#pragma unroll
            for (int nt = 0; nt < 4; nt++) {
                mma16816(acc[pt][nt], aH[pt], bH[nt]);
                mma16816(acc[pt][nt], aL[pt], bH[nt]);
                mma16816(acc[pt][nt], aH[pt], bL[nt]);
            }
    }

#pragma unroll
    for (int pt = 0; pt < 2; pt++)
#pragma unroll
        for (int half = 0; half < 2; half++) {
            long pp = (long)tq * 256 + warp_p + (pt << 4) + prow + (half << 3);
#pragma unroll
            for (int nt = 0; nt < 4; nt++) {
                int m = (nt << 3) + mcol;
                float v0 = fmaxf(acc[pt][nt][half * 2] + __ldg(&bias[m]), 0.f);
                float v1 = fmaxf(acc[pt][nt][half * 2 + 1] + __ldg(&bias[m + 1]), 0.f);
                uint32_t hw, lw;
                split2(v0, v1, hw, lw);
                *(uint32_t*)((char*)y2H + pp * 64 + m * 2) = hw;
                *(uint32_t*)((char*)y2L + pp * 64 + m * 2) = lw;
            }
        }
}

// ---------------- pool2 on bf16 pairs ----------------
__global__ void pool2_kernel(const __nv_bfloat16* __restrict__ y2H, const __nv_bfloat16* __restrict__ y2L,
                             __nv_bfloat16* __restrict__ p2H, __nv_bfloat16* __restrict__ p2L)
{
    int idx = blockIdx.x * 256 + threadIdx.x;
    if (idx >= 81152 * 16) return;
    int u = idx & 15;
    int ppp = idx >> 4;
    int b = ppp & 255, tq = ppp >> 8;
    const uint32_t* H = (const uint32_t*)y2H;
    const uint32_t* L = (const uint32_t*)y2L;
    long r0 = ((long)(2 * tq) * 256 + b) * 16 + u;
    float2 a0 = bf2f(H[r0]),        b0 = bf2f(L[r0]);
    float2 a1 = bf2f(H[r0 + 4096]), b1 = bf2f(L[r0 + 4096]);
    float2 a2 = bf2f(H[r0 + 8192]), b2 = bf2f(L[r0 + 8192]);
    float vx = fmaxf(fmaxf(a0.x + b0.x, a1.x + b1.x), a2.x + b2.x);
    float vy = fmaxf(fmaxf(a0.y + b0.y, a1.y + b1.y), a2.y + b2.y);
    uint32_t hw, lw;
    split2(vx, vy, hw, lw);
    ((uint32_t*)p2H)[(long)ppp * 16 + u] = hw;
    ((uint32_t*)p2L)[(long)ppp * 16 + u] = lw;
}

// ---------------- fc1 via mma: 2 t per iteration (K=64), dynamic smem ----------------
#define F1_APL 18432           // per-plane A: 128 rows x 144B
#define F1_OFF_W 36864
#define F1_SMEM 73728

__global__ void __launch_bounds__(256, 1) fc1_mma(
    const __nv_bfloat16* __restrict__ p2H, const __nv_bfloat16* __restrict__ p2L,
    const __nv_bfloat16* __restrict__ wH, const __nv_bfloat16* __restrict__ wL,
    float* __restrict__ part)
{
    extern __shared__ char sm[];
    uint32_t sb = s2u(sm);
    int tid = threadIdx.x;
    int b0 = blockIdx.x << 7, m0 = blockIdx.y << 7, z = blockIdx.z;
    int t1 = z * 40 + 40; if (t1 > 317) t1 = 317;

    int warp = tid >> 5, lane = tid & 31;
    int warp_p = (warp & 1) << 6;
    int warp_m = (warp >> 1) << 5;
    int arow = lane & 15, acol = (lane >> 4) << 3;
    int brow = lane & 7, bcol = ((lane >> 3) & 1) << 3;
    int prow = lane >> 2, mcol = (lane & 3) << 1;

    float acc[4][4][4];
#pragma unroll
    for (int pt = 0; pt < 4; pt++)
#pragma unroll
        for (int nt = 0; nt < 4; nt++)
#pragma unroll
            for (int j = 0; j < 4; j++) acc[pt][nt][j] = 0.f;

    for (int t = z * 40; t < t1; t += 2) {
        int hasT1 = (t + 1 < t1);
        __syncthreads();
#pragma unroll
        for (int l = 0; l < 8; l++) {
            int idx = tid + (l << 8);
            int plane = idx >> 10;
            int r = (idx >> 3) & 127;
            int c = idx & 7;
            int tt = t + (c >> 2);
            float4 v;
            if (c >= 4 && !hasT1) v = make_float4(0.f, 0.f, 0.f, 0.f);
            else v = *(const float4*)((plane ? p2L : p2H) + (long)(tt * 256 + b0 + r) * 32 + (c & 3) * 8);
            *(float4*)(sm + plane * F1_APL + r * 144 + c * 16) = v;
        }
#pragma unroll
        for (int l = 0; l < 8; l++) {
            int idx = tid + (l << 8);
            int plane = idx >> 10;
            int r = (idx >> 3) & 127;
            int c = idx & 7;
            float4 v;
            if (c >= 4 && !hasT1) v = make_float4(0.f, 0.f, 0.f, 0.f);
            else v = *(const float4*)((plane ? wL : wH) + (long)(m0 + r) * 10144 + t * 32 + c * 8);
            *(float4*)(sm + F1_OFF_W + plane * F1_APL + r * 144 + c * 16) = v;
        }
        __syncthreads();
#pragma unroll
        for (int ks = 0; ks < 4; ks++) {
            uint32_t aH[4][4], aL[4][4], bH[4][2], bL[4][2];
#pragma unroll
            for (int pt = 0; pt < 4; pt++) {
                uint32_t o = (uint32_t)((warp_p + (pt << 4) + arow) * 144 + (((ks << 4) + acol) << 1));
                ldm_x4(aH[pt], sb + o);
                ldm_x4(aL[pt], sb + F1_APL + o);
            }
#pragma unroll
            for (int nt = 0; nt < 4; nt++) {
                uint32_t o = F1_OFF_W + (uint32_t)((warp_m + (nt << 3) + brow) * 144 + (((ks << 4) + bcol) << 1));
                ldm_x2(bH[nt], sb + o);
                ldm_x2(bL[nt], sb + F1_APL + o);
            }
#pragma unroll
            for (int pt = 0; pt < 4; pt++)
#pragma unroll
                for (int nt = 0; nt < 4; nt++) {
                    mma16816(acc[pt][nt], aH[pt], bH[nt]);
                    mma16816(acc[pt][nt], aL[pt], bH[nt]);
                    mma16816(acc[pt][nt], aH[pt], bL[nt]);
                }
        }
    }

#pragma unroll
    for (int pt = 0; pt < 4; pt++)
#pragma unroll
        for (int half = 0; half < 2; half++) {
            int b = b0 + warp_p + (pt << 4) + prow + (half << 3);
#pragma unroll
            for (int nt = 0; nt < 4; nt++) {
                int m = m0 + warp_m + (nt << 3) + mcol;
                part[(long)z * 262144 + m * 256 + b] = acc[pt][nt][half * 2];
                part[(long)z * 262144 + (m + 1) * 256 + b] = acc[pt][nt][half * 2 + 1];
            }
        }
}

// ---------------- 64x64 fp32 GEMM with split-K (fc2 only) ----------------
template <class AL, class BL, class EP>
__global__ void __launch_bounds__(256) gemm64_kernel(int totKB, int splitKB, AL al, BL bl, EP ep)
{
    __shared__ float As[32][68];
    __shared__ float Bs[32][68];
    int mBase = blockIdx.y << 6;
    int pBase = blockIdx.x << 6;
    int kb0 = blockIdx.z * splitKB;
    int kb1 = kb0 + splitKB; if (kb1 > totKB) kb1 = totKB;
    int tid = threadIdx.x;
    int tx = tid & 15, ty = tid >> 4;
    float acc[4][4];
#pragma unroll
    for (int i = 0; i < 4; i++)
#pragma unroll
        for (int j = 0; j < 4; j++) acc[i][j] = 0.f;

    for (int kb = kb0; kb < kb1; kb++) {
        int k0 = kb << 5;
#pragma unroll
        for (int i = 0; i < 8; i++) {
            int idx = tid + (i << 8);
            int m = idx >> 5, k = idx & 31;
            As[k][m] = al(mBase + m, k0 + k);
        }
#pragma unroll
        for (int i = 0; i < 8; i++) {
            int idx = tid + (i << 8);
            int k = idx >> 6, p = idx & 63;
            Bs[k][p] = bl(k0 + k, pBase + p);
        }
        __syncthreads();
#pragma unroll
        for (int k = 0; k < 32; k++) {
            float4 a4 = *(const float4*)&As[k][ty << 2];
            float4 b4 = *(const float4*)&Bs[k][tx << 2];
            float a[4] = {a4.x, a4.y, a4.z, a4.w};
            float bb[4] = {b4.x, b4.y, b4.z, b4.w};
#pragma unroll
            for (int i = 0; i < 4; i++)
#pragma unroll
                for (int j = 0; j < 4; j++) acc[i][j] += a[i] * bb[j];
        }
        __syncthreads();
    }
#pragma unroll
    for (int i = 0; i < 4; i++) {
        int m = mBase + (ty << 2) + i;
#pragma unroll
        for (int j = 0; j < 4; j++) {
            int p = pBase + (tx << 2) + j;
            ep.store(m, p, acc[i][j]);
        }
    }
}

struct ALRowG {
    const float* A; int K, M;
    __device__ float operator()(int m, int k) const {
        return (m < M) ? A[m * K + k] : 0.f;
    }
};
struct BLRow {
    const float* B; int N;
    __device__ float operator()(int k, int p) const { return B[k * N + p]; }
};
struct EPPart {
    float* out; int Mstride;
    __device__ void store(int m, int p, float v) const {
        out[blockIdx.z * Mstride + m * 256 + p] = v;
    }
};

// ---------------- split-K reduce + bias + relu ----------------
__global__ void reduce_kernel(const float* __restrict__ part, const float* __restrict__ bias,
                              float* __restrict__ out, int S, int Mstride, int total)
{
    int idx = blockIdx.x * 256 + threadIdx.x;
    if (idx >= total) return;
    int m = idx >> 8;
    float s = 0.f;
    for (int z = 0; z < S; z++) s += part[z * Mstride + idx];
    out[idx] = fmaxf(s + bias[m], 0.f);
}

// ---------------- fc3 + softmax + argmax ----------------
__global__ void fc3_softmax_kernel(const float* __restrict__ F2, const float* __restrict__ W3,
                                   const float* __restrict__ B3, float* __restrict__ out)
{
    int b = threadIdx.x;
    float l0 = B3[0], l1 = B3[1];
#pragma unroll 8
    for (int k = 0; k < 256; k++) {
        float v = F2[k * 256 + b];
        l0 += W3[k] * v;
        l1 += W3[256 + k] * v;
    }
    out[2 * b] = l0;
    out[2 * b + 1] = l1;
    float mx = fmaxf(l0, l1);
    float e0 = __expf(l0 - mx), e1 = __expf(l1 - mx);
    float inv = 1.f / (e0 + e1);
    out[512 + 2 * b] = e0 * inv;
    out[512 + 2 * b + 1] = e1 * inv;
    out[1024 + b] = (l1 > l0) ? 1.f : 0.f;
}

// ---------------- host orchestration ----------------
extern "C" void kernel_launch(void* const* d_in, const int* in_sizes, int n_in,
                              void* d_out, int out_size)
{
    const float* x        = (const float*)d_in[0];
    const float* start_w  = (const float*)d_in[1];
    const float* filter_w = (const float*)d_in[2];
    const float* gate_w   = (const float*)d_in[3];
    const float* res_w    = (const float*)d_in[4];
    const float* skip_w   = (const float*)d_in[5];
    const float* end1_w   = (const float*)d_in[6];
    const float* end1_b   = (const float*)d_in[7];
    const float* end2_w   = (const float*)d_in[8];
    const float* end2_b   = (const float*)d_in[9];
    const float* fc_w1    = (const float*)d_in[10];
    const float* fc_b1    = (const float*)d_in[11];
    const float* fc_w2    = (const float*)d_in[12];
    const float* fc_b2    = (const float*)d_in[13];
    const float* fc_w3    = (const float*)d_in[14];
    const float* fc_b3    = (const float*)d_in[15];

    float *r1, *r2, *G, *skipbuf, *y1, *y2, *p2, *f1p, *f1, *f2;
    __nv_bfloat16 *wtc, *wl;
    cudaGetSymbolAddress((void**)&r1, g_r1);
    cudaGetSymbolAddress((void**)&r2, g_r2);
    cudaGetSymbolAddress((void**)&G, g_G);
    cudaGetSymbolAddress((void**)&skipbuf, g_skip);
    cudaGetSymbolAddress((void**)&y1, g_y1);
    cudaGetSymbolAddress((void**)&y2, g_y2);
    cudaGetSymbolAddress((void**)&p2, g_p2);
    cudaGetSymbolAddress((void**)&f1p, g_f1p);
    cudaGetSymbolAddress((void**)&f1, g_f1);
    cudaGetSymbolAddress((void**)&f2, g_f2);
    cudaGetSymbolAddress((void**)&wtc, g_wtc);
    cudaGetSymbolAddress((void**)&wl, g_wlay);

    __nv_bfloat16* gtH = (__nv_bfloat16*)G;
    __nv_bfloat16* gtL = gtH + (long)NP * 192;
    __nv_bfloat16* wskH = wtc;
    __nv_bfloat16* wskL = wtc + 49152;
    __nv_bfloat16* we1H = wtc + 98304;
    __nv_bfloat16* we1L = wtc + 131072;

    __nv_bfloat16* s1H = (__nv_bfloat16*)r1;
    __nv_bfloat16* s1L = s1H + 10485760;
    __nv_bfloat16* s2H = (__nv_bfloat16*)r2;
    __nv_bfloat16* s2L = s2H + 10485760;

    __nv_bfloat16* y1H = (__nv_bfloat16*)y1;
    __nv_bfloat16* y1L = y1H + (long)NP * 128;
    __nv_bfloat16* y2H = (__nv_bfloat16*)y2;
    __nv_bfloat16* y2L = y2H + (long)162560 * 32;
    __nv_bfloat16* p2H = (__nv_bfloat16*)p2;
    __nv_bfloat16* p2L = p2H + (long)81152 * 32;

    __nv_bfloat16* wf1H = (__nv_bfloat16*)skipbuf;
    __nv_bfloat16* wf1L = wf1H + 10387456;
    __nv_bfloat16* we2H = wf1L + 10387456;
    __nv_bfloat16* we2L = we2H + 4096;

    cudaFuncSetAttribute(layer_mma, cudaFuncAttributeMaxDynamicSharedMemorySize, L_SMEM);
    cudaFuncSetAttribute(mega_gemm, cudaFuncAttributeMaxDynamicSharedMemorySize, MG_SMEM);
    cudaFuncSetAttribute(end2_mma, cudaFuncAttributeMaxDynamicSharedMemorySize, E2_SMEM);
    cudaFuncSetAttribute(fc1_mma, cudaFuncAttributeMaxDynamicSharedMemorySize, F1_SMEM);

    // preps first
    prepw_kernel<<<320, 256>>>(skip_w, end1_w, wtc);
    prepl_kernel<<<136, 256>>>(filter_w, gate_w, res_w, wl, end2_w, we2H, we2L);
    prepfc_kernel<<<1024, 256>>>(fc_w1, wf1H, wf1L);
    // fused transpose + start conv -> stream planes in r1
    start_fused<<<320, 256>>>(x, start_w, s1H, s1L);

    // layers (128 q-rows per block, 2 CTAs/SM)
    const int QQ[6]  = {327424, 327168, 326656, 326400, 326144, 325632};
    const int NR[6]  = {256, 512, 1024, 256, 512, 1024};
    const int SS[6]  = {0, 256, 512, 0, 256, 512};
    const int OFF[6] = {1792, 1536, 1024, 768, 512, 0};

    __nv_bfloat16 *curH = s1H, *curL = s1L, *nxtH = s2H, *nxtL = s2L;
    for (int i = 0; i < 6; i++) {
        int nblk = QQ[i] >> 7;
        layer_mma<<<nblk, 256, L_SMEM>>>(curH, curL, wl + i * 10240,
                                         gtH, gtL, nxtH, nxtL,
                                         NR[i], SS[i], OFF[i], i * 64, (i < 5) ? 1 : 0);
        __nv_bfloat16* t;
        t = curH; curH = nxtH; nxtH = t;
        t = curL; curL = nxtL; nxtL = t;
    }

    // fused skip + end1 -> y1 pairs
    mega_gemm<<<NP / 128, 256, MG_SMEM>>>(gtH, gtL, wskH, wskL, we1H, we1L, end1_b, y1H, y1L);

    // fused pool1 + end2 -> y2 pairs
    end2_mma<<<635, 256, E2_SMEM>>>(y1H, y1L, we2H, we2L, end2_b, y2H, y2L);

    // pool2 -> p2 pairs
    pool2_kernel<<<(81152 * 16 + 255) / 256, 256>>>(y2H, y2L, p2H, p2L);

    // fc1 (mma, split-K=8, 2 t per iter) -> partials -> reduce(+bias,relu) -> f1 fp32
    {
        dim3 gg(2, 8, 8);
        fc1_mma<<<gg, 256, F1_SMEM>>>(p2H, p2L, wf1H, wf1L, f1p);
        int total = 1024 * 256;
        reduce_kernel<<<(total + 255) / 256, 256>>>(f1p, fc_b1, f1, 8, total, total);
    }
    // fc2: 256 x 1024 x 256, fp32 split-K=8 (reuses f1p for partials)
    {
        ALRowG al = {fc_w2, 1024, 256};
        BLRow bl = {f1, 256};
        EPPart ep = {f1p, 256 * 256};
        dim3 gg(4, 4, 8);
        gemm64_kernel<<<gg, 256>>>(32, 4, al, bl, ep);
        int total = 256 * 256;
        reduce_kernel<<<(total + 255) / 256, 256>>>(f1p, fc_b2, f2, 8, total, total);
    }
    // fc3 + softmax + argmax
    fc3_softmax_kernel<<<1, 256>>>(f2, fc_w3, fc_b3, (float*)d_out);
}